// round 1
// baseline (speedup 1.0000x reference)
#include <cuda_runtime.h>
#include <math.h>

// ---------------- problem constants ----------------
#define HWp   1600            // 40*40 pixels, contiguous innermost
#define B_    32
#define C1_   1024
#define HID_  512
#define C2_   1024
#define KCAT  2048
#define N1    (HID_*C1_)      // 524288  (w1 elements)
#define N2    (C2_*KCAT)      // 2097152 (w2 elements)

// ---------------- scratch (device globals; no allocs allowed) ----------------
__device__ float g_h [(size_t)B_*HID_*HWp];
__device__ float g_y1[(size_t)B_*HID_*HWp];
__device__ float g_y2[(size_t)B_*HID_*HWp];
__device__ float g_y3[(size_t)B_*HID_*HWp];
__device__ float g_w1q[N1];
__device__ float g_w2q[N2];
__device__ float g_A1[HID_], g_B1[HID_];
__device__ float g_A2[C2_],  g_B2[C2_];
__device__ float g_sc[2];          // s1, s2 (median scales)
__device__ float g_kth[2];         // two middle order statistics
__device__ unsigned g_hist[256];
__device__ unsigned g_sel[2];      // [0]=prefix bits, [1]=remaining rank

// ---------------- exact median via radix-select on |w| bit patterns ----------
// nonnegative floats order identically to their uint32 bit patterns.

__global__ void k_selinit(unsigned k) {
    if (threadIdx.x == 0) { g_sel[0] = 0u; g_sel[1] = k; }
    for (int i = threadIdx.x; i < 256; i += blockDim.x) g_hist[i] = 0u;
}

__global__ void k_hist(const float* __restrict__ w, unsigned n, int level) {
    __shared__ unsigned sh[256];
    for (int i = threadIdx.x; i < 256; i += blockDim.x) sh[i] = 0u;
    __syncthreads();
    const unsigned prefix   = g_sel[0];
    const unsigned maskHigh = (level == 3) ? 0u : (0xFFFFFFFFu << ((level + 1) * 8));
    const int shift = level * 8;
    for (unsigned i = blockIdx.x * blockDim.x + threadIdx.x; i < n;
         i += gridDim.x * blockDim.x) {
        unsigned u = __float_as_uint(w[i]) & 0x7FFFFFFFu;
        if ((u & maskHigh) == (prefix & maskHigh))
            atomicAdd(&sh[(u >> shift) & 255u], 1u);
    }
    __syncthreads();
    for (int i = threadIdx.x; i < 256; i += blockDim.x)
        if (sh[i]) atomicAdd(&g_hist[i], sh[i]);
}

__global__ void k_pick(int level, int slot) {
    // single thread: choose bucket containing the remaining rank
    unsigned k = g_sel[1];
    unsigned cum = 0; int b = 0;
    for (; b < 256; ++b) {
        unsigned c = g_hist[b];
        if (cum + c > k) break;
        cum += c;
    }
    g_sel[0] |= ((unsigned)b) << (level * 8);
    g_sel[1]  = k - cum;
    for (int i = 0; i < 256; ++i) g_hist[i] = 0u;
    if (level == 0) g_kth[slot] = __uint_as_float(g_sel[0]);
}

__global__ void k_combine(int sidx) {
    // jnp.median for even n: mean of the two middle values (fp32)
    g_sc[sidx] = fmaxf(0.5f * (g_kth[0] + g_kth[1]), 1e-8f);
}

// ---------------- ternary quantization: store codes in {-1,0,+1} as float ----
__global__ void k_quant(const float* __restrict__ w, unsigned n, int sidx, int which) {
    float* q = (which == 0) ? g_w1q : g_w2q;
    const float inv_s_src = g_sc[sidx];
    for (unsigned i = blockIdx.x * blockDim.x + threadIdx.x; i < n;
         i += gridDim.x * blockDim.x) {
        float t = rintf(w[i] / inv_s_src);     // round-half-even, same as jnp.round
        t = fminf(fmaxf(t, -1.0f), 1.0f);
        q[i] = t;
    }
}

// ---------------- BN epilogue constants (scale s folded into multiplier) ----
__global__ void k_bnparams(const float* __restrict__ g, const float* __restrict__ b,
                           const float* __restrict__ m, const float* __restrict__ v,
                           int n, int sidx, int which) {
    float* A  = (which == 0) ? g_A1 : g_A2;
    float* Bc = (which == 0) ? g_B1 : g_B2;
    const float s = g_sc[sidx];
    int i = blockIdx.x * blockDim.x + threadIdx.x;
    if (i < n) {
        float inv = g[i] * __frsqrt_rn(v[i] + 1e-5f);
        A[i]  = inv * s;
        Bc[i] = b[i] - m[i] * inv;
    }
}

// ---------------- fused GEMM + BN + SiLU ------------------------------------
// Per-batch GEMM: Out[b][m][0..1599] = silu( (sum_k Wq[m][k] * X[b][k][n]) * A[m] + B[m] )
// BM=128 (out channels), BN=64 (pixels), BK=8, 256 threads, 8x4 per thread,
// double-buffered smem.

__device__ __forceinline__ float silu(float y) {
    return y / (1.0f + expf(-y));
}

template<int LAYER>
__global__ __launch_bounds__(256)
void k_gemm(const float* __restrict__ Xext, float* __restrict__ OutExt) {
    constexpr int K = (LAYER == 1) ? C1_ : KCAT;
    constexpr int M = (LAYER == 1) ? HID_ : C2_;
    const float* __restrict__ Wq = (LAYER == 1) ? g_w1q : g_w2q;
    const float* __restrict__ Ae = (LAYER == 1) ? g_A1  : g_A2;
    const float* __restrict__ Be = (LAYER == 1) ? g_B1  : g_B2;
    float* Out = (LAYER == 1) ? g_h : OutExt;

    const int b   = blockIdx.z;
    const int n0  = blockIdx.x * 64;
    const int m0  = blockIdx.y * 128;
    const int tid = threadIdx.x;

    __shared__ float As[2][8][128];
    __shared__ float Bs[2][8][64];

    float acc[8][4];
#pragma unroll
    for (int i = 0; i < 8; ++i)
#pragma unroll
        for (int j = 0; j < 4; ++j) acc[i][j] = 0.0f;

    // A-load mapping: 128 rows x 2 float4 -> one float4 per thread
    const int arow  = tid >> 1;
    const int apart = tid & 1;
    const float* aptr = Wq + (size_t)(m0 + arow) * K + apart * 4;

    // B-load mapping: 8 rows x 16 float4 -> tid<128, one float4 each
    const int bk = tid >> 4;       // 0..7 (only valid tid<128)
    const int bc = tid & 15;       // 0..15

    const int tn0 = (tid & 15) * 4;
    const int tm0 = (tid >> 4) * 8;

    const int nt = K / 8;

    float4 ra, rb;
    rb = make_float4(0.f, 0.f, 0.f, 0.f);

    auto loadTile = [&](int t) {
        const int k0 = t * 8;
        ra = *(const float4*)(aptr + k0);
        if (tid < 128) {
            if (LAYER == 1) {
                rb = *(const float4*)(Xext + ((size_t)b * K + (k0 + bk)) * HWp
                                      + n0 + bc * 4);
            } else {
                int kk = k0 + bk;
                int src = kk >> 9;
                int cc  = kk & 511;
                const float* Xs = (src == 0) ? g_h : (src == 1) ? g_y1
                                 : (src == 2) ? g_y2 : g_y3;
                rb = *(const float4*)(Xs + ((size_t)b * HID_ + cc) * HWp
                                      + n0 + bc * 4);
            }
        }
    };
    auto storeTile = [&](int s) {
        As[s][apart * 4 + 0][arow] = ra.x;
        As[s][apart * 4 + 1][arow] = ra.y;
        As[s][apart * 4 + 2][arow] = ra.z;
        As[s][apart * 4 + 3][arow] = ra.w;
        if (tid < 128) *(float4*)&Bs[s][bk][bc * 4] = rb;
    };

    loadTile(0);
    storeTile(0);
    __syncthreads();

    for (int t = 0; t < nt; ++t) {
        const int s = t & 1;
        if (t + 1 < nt) loadTile(t + 1);
#pragma unroll
        for (int k = 0; k < 8; ++k) {
            float4 b4 = *(const float4*)&Bs[s][k][tn0];
            float4 a0 = *(const float4*)&As[s][k][tm0];
            float4 a1 = *(const float4*)&As[s][k][tm0 + 4];
            float av[8] = {a0.x, a0.y, a0.z, a0.w, a1.x, a1.y, a1.z, a1.w};
            float bv[4] = {b4.x, b4.y, b4.z, b4.w};
#pragma unroll
            for (int i = 0; i < 8; ++i)
#pragma unroll
                for (int j = 0; j < 4; ++j) acc[i][j] += av[i] * bv[j];
        }
        if (t + 1 < nt) storeTile(s ^ 1);
        __syncthreads();
    }

    // epilogue: BN + SiLU, vectorized store
#pragma unroll
    for (int i = 0; i < 8; ++i) {
        const int m = m0 + tm0 + i;
        const float a  = Ae[m];
        const float bb = Be[m];
        float4 r;
        r.x = silu(acc[i][0] * a + bb);
        r.y = silu(acc[i][1] * a + bb);
        r.z = silu(acc[i][2] * a + bb);
        r.w = silu(acc[i][3] * a + bb);
        *(float4*)(Out + ((size_t)b * M + m) * HWp + n0 + tn0) = r;
    }
}

// ---------------- 5x5 stride-1 pad-2 maxpool (separable, one plane/block) ---
__global__ __launch_bounds__(256)
void k_pool(int stage) {
    const float* in  = (stage == 0) ? g_h  : (stage == 1) ? g_y1 : g_y2;
    float*       out = (stage == 0) ? g_y1 : (stage == 1) ? g_y2 : g_y3;

    __shared__ float p[HWp];
    __shared__ float tmp[HWp];
    const size_t plane = (size_t)blockIdx.x * HWp;
    const int tid = threadIdx.x;

    for (int i = tid; i < HWp; i += 256) p[i] = in[plane + i];
    __syncthreads();
    for (int i = tid; i < HWp; i += 256) {
        int y = i / 40, x = i % 40;
        float m = p[i];
        int x0 = max(x - 2, 0), x1 = min(x + 2, 39);
        for (int xx = x0; xx <= x1; ++xx) m = fmaxf(m, p[y * 40 + xx]);
        tmp[i] = m;
    }
    __syncthreads();
    for (int i = tid; i < HWp; i += 256) {
        int y = i / 40, x = i % 40;
        float m = tmp[i];
        int y0 = max(y - 2, 0), y1 = min(y + 2, 39);
        for (int yy = y0; yy <= y1; ++yy) m = fmaxf(m, tmp[yy * 40 + x]);
        out[plane + i] = m;
    }
}

// ---------------- host orchestration (all graph-capturable launches) --------
static void run_select(const float* w, unsigned n, unsigned k, int slot) {
    k_selinit<<<1, 256>>>(k);
    for (int level = 3; level >= 0; --level) {
        k_hist<<<256, 256>>>(w, n, level);
        k_pick<<<1, 1>>>(level, slot);
    }
}

extern "C" void kernel_launch(void* const* d_in, const int* in_sizes, int n_in,
                              void* d_out, int out_size) {
    const float* x  = (const float*)d_in[0];
    const float* w1 = (const float*)d_in[1];
    const float* g1 = (const float*)d_in[2];
    const float* b1 = (const float*)d_in[3];
    const float* m1 = (const float*)d_in[4];
    const float* v1 = (const float*)d_in[5];
    const float* w2 = (const float*)d_in[6];
    const float* g2 = (const float*)d_in[7];
    const float* b2 = (const float*)d_in[8];
    const float* m2 = (const float*)d_in[9];
    const float* v2 = (const float*)d_in[10];
    float* out = (float*)d_out;

    // exact medians: even n -> mean of two middle order statistics
    run_select(w1, N1, N1 / 2 - 1, 0);
    run_select(w1, N1, N1 / 2,     1);
    k_combine<<<1, 1>>>(0);
    run_select(w2, N2, N2 / 2 - 1, 0);
    run_select(w2, N2, N2 / 2,     1);
    k_combine<<<1, 1>>>(1);

    // quantize weights to ternary codes
    k_quant<<<1024, 256>>>(w1, N1, 0, 0);
    k_quant<<<2048, 256>>>(w2, N2, 1, 1);

    // BN epilogue constants (fold s into multiplier)
    k_bnparams<<<(HID_ + 255) / 256, 256>>>(g1, b1, m1, v1, HID_, 0, 0);
    k_bnparams<<<(C2_  + 255) / 256, 256>>>(g2, b2, m2, v2, C2_,  1, 1);

    // layer 1: conv1x1 + BN + SiLU -> g_h
    {
        dim3 grid(HWp / 64, HID_ / 128, B_);
        k_gemm<1><<<grid, 256>>>(x, nullptr);
    }

    // cascaded 5x5 maxpools
    k_pool<<<B_ * HID_, 256>>>(0);
    k_pool<<<B_ * HID_, 256>>>(1);
    k_pool<<<B_ * HID_, 256>>>(2);

    // layer 2: conv1x1 over virtual concat + BN + SiLU -> out
    {
        dim3 grid(HWp / 64, C2_ / 128, B_);
        k_gemm<2><<<grid, 256>>>(nullptr, out);
    }
}

// round 7
// speedup vs baseline: 3.9407x; 3.9407x over previous
#include <cuda_runtime.h>
#include <cuda_fp16.h>
#include <math.h>

// ---------------- problem constants ----------------
#define HWp   1600            // 40*40 pixels, contiguous innermost
#define B_    32
#define C1_   1024
#define HID_  512
#define C2_   1024
#define KCAT  2048
#define N1    (HID_*C1_)      // 524288  (w1 elements)
#define N2    (C2_*KCAT)      // 2097152 (w2 elements)

// GEMM tiling
#define BM 128
#define BN 64
#define BK 32

// ---------------- scratch (device globals; no allocs allowed) ----------------
// NOTE: these symbols are ONLY referenced from device code (never passed as
// kernel arguments from host) — host-side use of a __device__ symbol yields the
// host BSS shadow address and trips HMM page migration (the 126-128 MiB deltas
// of rounds 2-6).
__device__ __half g_xh[(size_t)B_*C1_*HWp];   // x in fp16
__device__ __half g_h [(size_t)B_*HID_*HWp];
__device__ __half g_y1[(size_t)B_*HID_*HWp];
__device__ __half g_y2[(size_t)B_*HID_*HWp];
__device__ __half g_y3[(size_t)B_*HID_*HWp];
__device__ __half g_w1q[N1];
__device__ __half g_w2q[N2];
__device__ float g_A1[HID_], g_B1[HID_];
__device__ float g_A2[C2_],  g_B2[C2_];
__device__ float g_sc[2];          // s1, s2 (median scales)
__device__ float g_kth[2];         // two middle order statistics
__device__ unsigned g_hist[256];
__device__ unsigned g_sel[2];      // [0]=prefix bits, [1]=remaining rank

// ---------------- cp.async helpers ------------------------------------------
__device__ __forceinline__ void cp16(void* smem_dst, const void* gmem_src) {
    unsigned d = (unsigned)__cvta_generic_to_shared(smem_dst);
    asm volatile("cp.async.cg.shared.global [%0], [%1], 16;" :: "r"(d), "l"(gmem_src));
}
__device__ __forceinline__ void cp_commit() {
    asm volatile("cp.async.commit_group;");
}
__device__ __forceinline__ void cp_wait0() {
    asm volatile("cp.async.wait_group 0;");
}

// ---------------- scalar-only mma / ldmatrix macros --------------------------
#define LDSM4(r0,r1,r2,r3,addr) \
    asm volatile("ldmatrix.sync.aligned.m8n8.x4.shared.b16 {%0,%1,%2,%3}, [%4];" \
        : "=r"(r0), "=r"(r1), "=r"(r2), "=r"(r3) : "r"(addr))

#define LDSM4T(r0,r1,r2,r3,addr) \
    asm volatile("ldmatrix.sync.aligned.m8n8.x4.trans.shared.b16 {%0,%1,%2,%3}, [%4];" \
        : "=r"(r0), "=r"(r1), "=r"(r2), "=r"(r3) : "r"(addr))

#define MMA16816(d0,d1,d2,d3,aa0,aa1,aa2,aa3,bb0,bb1) \
    asm volatile("mma.sync.aligned.m16n8k16.row.col.f32.f16.f16.f32 " \
        "{%0,%1,%2,%3}, {%4,%5,%6,%7}, {%8,%9}, {%0,%1,%2,%3};" \
        : "+f"(d0), "+f"(d1), "+f"(d2), "+f"(d3) \
        : "r"(aa0), "r"(aa1), "r"(aa2), "r"(aa3), "r"(bb0), "r"(bb1))

#define DECL_C(p) float p##0 = 0.f, p##1 = 0.f, p##2 = 0.f, p##3 = 0.f

// ---------------- exact median via radix-select on |w| bit patterns ----------
// (verbatim from the passing Round-1 kernel)

__global__ void k_selinit(unsigned k) {
    if (threadIdx.x == 0) { g_sel[0] = 0u; g_sel[1] = k; }
    for (int i = threadIdx.x; i < 256; i += blockDim.x) g_hist[i] = 0u;
}

__global__ void k_hist(const float* __restrict__ w, unsigned n, int level) {
    __shared__ unsigned sh[256];
    for (int i = threadIdx.x; i < 256; i += blockDim.x) sh[i] = 0u;
    __syncthreads();
    const unsigned prefix   = g_sel[0];
    const unsigned maskHigh = (level == 3) ? 0u : (0xFFFFFFFFu << ((level + 1) * 8));
    const int shift = level * 8;
    for (unsigned i = blockIdx.x * blockDim.x + threadIdx.x; i < n;
         i += gridDim.x * blockDim.x) {
        unsigned u = __float_as_uint(w[i]) & 0x7FFFFFFFu;
        if ((u & maskHigh) == (prefix & maskHigh))
            atomicAdd(&sh[(u >> shift) & 255u], 1u);
    }
    __syncthreads();
    for (int i = threadIdx.x; i < 256; i += blockDim.x)
        if (sh[i]) atomicAdd(&g_hist[i], sh[i]);
}

__global__ void k_pick(int level, int slot) {
    unsigned k = g_sel[1];
    unsigned cum = 0; int b = 0;
    for (; b < 256; ++b) {
        unsigned c = g_hist[b];
        if (cum + c > k) break;
        cum += c;
    }
    g_sel[0] |= ((unsigned)b) << (level * 8);
    g_sel[1]  = k - cum;
    for (int i = 0; i < 256; ++i) g_hist[i] = 0u;
    if (level == 0) g_kth[slot] = __uint_as_float(g_sel[0]);
}

__global__ void k_combine(int sidx) {
    // jnp.median for even n: mean of the two middle values (fp32)
    g_sc[sidx] = fmaxf(0.5f * (g_kth[0] + g_kth[1]), 1e-8f);
}

// ---------------- ternary quantization: codes {-1,0,+1} as fp16 (exact) -----
__global__ void k_quant(const float* __restrict__ w, unsigned n, int sidx, int which) {
    __half* q = (which == 0) ? g_w1q : g_w2q;
    const float s = g_sc[sidx];
    for (unsigned i = blockIdx.x * blockDim.x + threadIdx.x; i < n;
         i += gridDim.x * blockDim.x) {
        float t = rintf(w[i] / s);              // round-half-even == jnp.round
        t = fminf(fmaxf(t, -1.0f), 1.0f);
        q[i] = __float2half(t);
    }
}

// ---------------- x fp32 -> fp16 --------------------------------------------
__global__ void k_cvt(const float* __restrict__ x, unsigned n2) {
    __half2* o2 = (__half2*)g_xh;
    for (unsigned i = blockIdx.x * blockDim.x + threadIdx.x; i < n2;
         i += gridDim.x * blockDim.x) {
        float2 v = ((const float2*)x)[i];
        o2[i] = __floats2half2_rn(v.x, v.y);
    }
}

// ---------------- BN epilogue constants (scale s folded into multiplier) ----
__global__ void k_bnparams(const float* __restrict__ g, const float* __restrict__ b,
                           const float* __restrict__ m, const float* __restrict__ v,
                           int n, int sidx, int which) {
    float* A  = (which == 0) ? g_A1 : g_A2;
    float* Bc = (which == 0) ? g_B1 : g_B2;
    const float s = g_sc[sidx];
    int i = blockIdx.x * blockDim.x + threadIdx.x;
    if (i < n) {
        float inv = g[i] * __frsqrt_rn(v[i] + 1e-5f);
        A[i]  = inv * s;
        Bc[i] = b[i] - m[i] * inv;
    }
}

// ---------------- fused tensor-core GEMM + BN + SiLU ------------------------
// Per-batch GEMM: Out[b][m][n] = silu( (sum_k Wq[m][k] * X[b][k][n]) * A[m] + B[m] )
// mma.sync.m16n8k16 fp16/fp32-acc. 8 warps as 4(M) x 2(N), warp tile 32x32.
// All global tensors referenced via device symbols inside the kernel.

__device__ __forceinline__ float silu(float y) {
    return y / (1.0f + expf(-y));
}

template<int LAYER>
__global__ __launch_bounds__(256)
void k_gemm_mma(float* __restrict__ OutExt) {
    constexpr int K = (LAYER == 1) ? C1_ : KCAT;
    const __half* __restrict__ Wq = (LAYER == 1) ? g_w1q : g_w2q;
    const float* __restrict__ Ae = (LAYER == 1) ? g_A1  : g_A2;
    const float* __restrict__ Be = (LAYER == 1) ? g_B1  : g_B2;

    const int b   = blockIdx.z;
    const int n0  = blockIdx.x * BN;
    const int m0  = blockIdx.y * BM;
    const int tid = threadIdx.x;
    const int lane = tid & 31;
    const int wid  = tid >> 5;
    const int wm = wid >> 1;   // 0..3 : 32-row slice
    const int wn = wid & 1;    // 0..1 : 32-col slice

    __shared__ __align__(16) __half As[2][BM][BK + 8];
    __shared__ __align__(16) __half Bs[2][BK][BN + 8];

    // 32 named accumulators: c{mt}{nt}{i}
    DECL_C(c00); DECL_C(c01); DECL_C(c02); DECL_C(c03);
    DECL_C(c10); DECL_C(c11); DECL_C(c12); DECL_C(c13);

    // async copy mappings (all 16B chunks)
    const int ar  = tid >> 2;        // A rows, chunk pass 1
    const int ac  = tid & 3;
    const int ar2 = (tid + 256) >> 2;
    const int br  = tid >> 3;        // B: 32 rows x 8 chunks
    const int bc  = tid & 7;

    auto issue = [&](int t, int s) {
        const int k0 = t * BK;
        cp16(&As[s][ar ][ac * 8], Wq + (size_t)(m0 + ar ) * K + k0 + ac * 8);
        cp16(&As[s][ar2][ac * 8], Wq + (size_t)(m0 + ar2) * K + k0 + ac * 8);
        const __half* src; size_t off;
        if (LAYER == 1) {
            src = g_xh;                                   // device symbol, device code
            off = ((size_t)b * K + (k0 + br)) * HWp;
        } else {
            int kk = k0 + br;
            int si = kk >> 9, cc = kk & 511;
            src = (si == 0) ? g_h : (si == 1) ? g_y1 : (si == 2) ? g_y2 : g_y3;
            off = ((size_t)b * HID_ + cc) * HWp;
        }
        cp16(&Bs[s][br][bc * 8], src + off + n0 + bc * 8);
        cp_commit();
    };

    issue(0, 0);
    cp_wait0();
    __syncthreads();

    const int lr = lane & 15;        // ldmatrix row-select
    const int lc = (lane >> 4) * 8;  // ldmatrix col-half select

    constexpr int NT = K / BK;
    for (int t = 0; t < NT; ++t) {
        const int s = t & 1;
        if (t + 1 < NT) issue(t + 1, s ^ 1);
#pragma unroll
        for (int kk = 0; kk < 2; ++kk) {
            const int k16 = kk * 16;
            unsigned b00, b01, b02, b03, b10, b11, b12, b13;
            unsigned a0, a1, a2, a3;
            {
                unsigned ad = (unsigned)__cvta_generic_to_shared(
                    &Bs[s][k16 + lr][wn * 32 + lc]);
                LDSM4T(b00, b01, b02, b03, ad);
            }
            {
                unsigned ad = (unsigned)__cvta_generic_to_shared(
                    &Bs[s][k16 + lr][wn * 32 + 16 + lc]);
                LDSM4T(b10, b11, b12, b13, ad);
            }
            {
                unsigned ad = (unsigned)__cvta_generic_to_shared(
                    &As[s][wm * 32 + lr][k16 + lc]);
                LDSM4(a0, a1, a2, a3, ad);
            }
            MMA16816(c000, c001, c002, c003, a0, a1, a2, a3, b00, b01);
            MMA16816(c010, c011, c012, c013, a0, a1, a2, a3, b02, b03);
            MMA16816(c020, c021, c022, c023, a0, a1, a2, a3, b10, b11);
            MMA16816(c030, c031, c032, c033, a0, a1, a2, a3, b12, b13);
            {
                unsigned ad = (unsigned)__cvta_generic_to_shared(
                    &As[s][wm * 32 + 16 + lr][k16 + lc]);
                LDSM4(a0, a1, a2, a3, ad);
            }
            MMA16816(c100, c101, c102, c103, a0, a1, a2, a3, b00, b01);
            MMA16816(c110, c111, c112, c113, a0, a1, a2, a3, b02, b03);
            MMA16816(c120, c121, c122, c123, a0, a1, a2, a3, b10, b11);
            MMA16816(c130, c131, c132, c133, a0, a1, a2, a3, b12, b13);
        }
        if (t + 1 < NT) cp_wait0();
        __syncthreads();
    }

    // epilogue: BN + SiLU (named scalars only)
#define STORE_TILE(cc, mtv, ntv) do {                                          \
        const int mrow = m0 + wm * 32 + (mtv) * 16 + (lane >> 2);              \
        const int col  = n0 + wn * 32 + (ntv) * 8 + (lane & 3) * 2;            \
        const float A0 = Ae[mrow],     Bv0 = Be[mrow];                         \
        const float A1 = Ae[mrow + 8], Bv1 = Be[mrow + 8];                     \
        float v0 = silu(cc##0 * A0 + Bv0), v1 = silu(cc##1 * A0 + Bv0);        \
        float v2 = silu(cc##2 * A1 + Bv1), v3 = silu(cc##3 * A1 + Bv1);        \
        if (LAYER == 1) {                                                      \
            *(__half2*)(g_h + ((size_t)b * HID_ + mrow) * HWp + col) =         \
                __floats2half2_rn(v0, v1);                                     \
            *(__half2*)(g_h + ((size_t)b * HID_ + mrow + 8) * HWp + col) =     \
                __floats2half2_rn(v2, v3);                                     \
        } else {                                                               \
            *(float2*)(OutExt + ((size_t)b * C2_ + mrow) * HWp + col) =        \
                make_float2(v0, v1);                                           \
            *(float2*)(OutExt + ((size_t)b * C2_ + mrow + 8) * HWp + col) =    \
                make_float2(v2, v3);                                           \
        }                                                                      \
    } while (0)

    STORE_TILE(c00, 0, 0); STORE_TILE(c01, 0, 1);
    STORE_TILE(c02, 0, 2); STORE_TILE(c03, 0, 3);
    STORE_TILE(c10, 1, 0); STORE_TILE(c11, 1, 1);
    STORE_TILE(c12, 1, 2); STORE_TILE(c13, 1, 3);
#undef STORE_TILE
}

// ---------------- 5x5 stride-1 pad-2 maxpool (separable, fp16) --------------
__global__ __launch_bounds__(256)
void k_pool(int stage) {
    const __half* in  = (stage == 0) ? g_h  : (stage == 1) ? g_y1 : g_y2;
    __half*       out = (stage == 0) ? g_y1 : (stage == 1) ? g_y2 : g_y3;

    __shared__ __half p[HWp];
    __shared__ __half tmp[HWp];
    const size_t plane = (size_t)blockIdx.x * HWp;
    const int tid = threadIdx.x;

    for (int i = tid; i < HWp; i += 256) p[i] = in[plane + i];
    __syncthreads();
    for (int i = tid; i < HWp; i += 256) {
        int y = i / 40, x = i % 40;
        __half m = p[i];
        int x0 = max(x - 2, 0), x1 = min(x + 2, 39);
        for (int xx = x0; xx <= x1; ++xx) m = __hmax(m, p[y * 40 + xx]);
        tmp[i] = m;
    }
    __syncthreads();
    for (int i = tid; i < HWp; i += 256) {
        int y = i / 40, x = i % 40;
        __half m = tmp[i];
        int y0 = max(y - 2, 0), y1 = min(y + 2, 39);
        for (int yy = y0; yy <= y1; ++yy) m = __hmax(m, tmp[yy * 40 + x]);
        out[plane + i] = m;
    }
}

// ---------------- host orchestration (all graph-capturable launches) --------
static void run_select(const float* w, unsigned n, unsigned k, int slot) {
    k_selinit<<<1, 256>>>(k);
    for (int level = 3; level >= 0; --level) {
        k_hist<<<256, 256>>>(w, n, level);
        k_pick<<<1, 1>>>(level, slot);
    }
}

extern "C" void kernel_launch(void* const* d_in, const int* in_sizes, int n_in,
                              void* d_out, int out_size) {
    const float* x  = (const float*)d_in[0];
    const float* w1 = (const float*)d_in[1];
    const float* g1 = (const float*)d_in[2];
    const float* b1 = (const float*)d_in[3];
    const float* m1 = (const float*)d_in[4];
    const float* v1 = (const float*)d_in[5];
    const float* w2 = (const float*)d_in[6];
    const float* g2 = (const float*)d_in[7];
    const float* b2 = (const float*)d_in[8];
    const float* m2 = (const float*)d_in[9];
    const float* v2 = (const float*)d_in[10];
    float* out = (float*)d_out;

    // convert activations to fp16 (writes device symbol from device code)
    k_cvt<<<2048, 256>>>(x, (unsigned)((size_t)B_ * C1_ * HWp / 2));

    // exact medians: even n -> mean of two middle order statistics
    run_select(w1, N1, N1 / 2 - 1, 0);
    run_select(w1, N1, N1 / 2,     1);
    k_combine<<<1, 1>>>(0);
    run_select(w2, N2, N2 / 2 - 1, 0);
    run_select(w2, N2, N2 / 2,     1);
    k_combine<<<1, 1>>>(1);

    // quantize weights to ternary fp16 codes
    k_quant<<<1024, 256>>>(w1, N1, 0, 0);
    k_quant<<<2048, 256>>>(w2, N2, 1, 1);

    // BN epilogue constants (fold s into multiplier)
    k_bnparams<<<(HID_ + 255) / 256, 256>>>(g1, b1, m1, v1, HID_, 0, 0);
    k_bnparams<<<(C2_  + 255) / 256, 256>>>(g2, b2, m2, v2, C2_,  1, 1);

    // layer 1: conv1x1 + BN + SiLU -> g_h (fp16)
    {
        dim3 grid(HWp / BN, HID_ / BM, B_);
        k_gemm_mma<1><<<grid, 256>>>(nullptr);
    }

    // cascaded 5x5 maxpools (fp16, exact)
    k_pool<<<B_ * HID_, 256>>>(0);
    k_pool<<<B_ * HID_, 256>>>(1);
    k_pool<<<B_ * HID_, 256>>>(2);

    // layer 2: conv1x1 over virtual concat + BN + SiLU -> out (fp32)
    {
        dim3 grid(HWp / BN, C2_ / BM, B_);
        k_gemm_mma<2><<<grid, 256>>>(out);
    }
}

// round 9
// speedup vs baseline: 4.1166x; 1.0446x over previous
#include <cuda_runtime.h>
#include <cuda_fp16.h>
#include <math.h>

// ---------------- problem constants ----------------
#define HWp   1600            // 40*40 pixels, contiguous innermost
#define B_    32
#define C1_   1024
#define HID_  512
#define C2_   1024
#define KCAT  2048
#define N1    (HID_*C1_)      // 524288  (w1 elements)
#define N2    (C2_*KCAT)      // 2097152 (w2 elements)

// GEMM tiling
#define BM 256
#define BN 64
#define BK 32
#define SMEM_GEMM (2*BM*(BK+8)*2 + 2*BK*(BN+8)*2)   // 50176 bytes (dynamic)

// ---------------- scratch (device globals; no allocs allowed) ----------------
// NOTE: referenced ONLY from device code (host-side use of a __device__ symbol
// yields the host BSS shadow and trips HMM migration — rounds 2-6 bug).
__device__ __half g_xh[(size_t)B_*C1_*HWp];   // x in fp16
__device__ __half g_h [(size_t)B_*HID_*HWp];
__device__ __half g_y1[(size_t)B_*HID_*HWp];
__device__ __half g_y2[(size_t)B_*HID_*HWp];
__device__ __half g_y3[(size_t)B_*HID_*HWp];
__device__ __half g_w1q[N1];
__device__ __half g_w2q[N2];
__device__ float g_A1[HID_], g_B1[HID_];
__device__ float g_A2[C2_],  g_B2[C2_];
__device__ float g_sc[2];              // s1, s2 (median scales)
__device__ unsigned g_pre[2];          // dual-rank radix-select prefixes
__device__ unsigned g_rank[2];         // remaining ranks
__device__ unsigned g_hist2[2][256];

// ---------------- cp.async helpers ------------------------------------------
__device__ __forceinline__ void cp16(void* smem_dst, const void* gmem_src) {
    unsigned d = (unsigned)__cvta_generic_to_shared(smem_dst);
    asm volatile("cp.async.cg.shared.global [%0], [%1], 16;" :: "r"(d), "l"(gmem_src));
}
__device__ __forceinline__ void cp_commit() {
    asm volatile("cp.async.commit_group;");
}
__device__ __forceinline__ void cp_wait0() {
    asm volatile("cp.async.wait_group 0;");
}

// ---------------- scalar-only mma / ldmatrix macros --------------------------
#define LDSM4(r0,r1,r2,r3,addr) \
    asm volatile("ldmatrix.sync.aligned.m8n8.x4.shared.b16 {%0,%1,%2,%3}, [%4];" \
        : "=r"(r0), "=r"(r1), "=r"(r2), "=r"(r3) : "r"(addr))

#define LDSM4T(r0,r1,r2,r3,addr) \
    asm volatile("ldmatrix.sync.aligned.m8n8.x4.trans.shared.b16 {%0,%1,%2,%3}, [%4];" \
        : "=r"(r0), "=r"(r1), "=r"(r2), "=r"(r3) : "r"(addr))

#define MMA16816(d0,d1,d2,d3,aa0,aa1,aa2,aa3,bb0,bb1) \
    asm volatile("mma.sync.aligned.m16n8k16.row.col.f32.f16.f16.f32 " \
        "{%0,%1,%2,%3}, {%4,%5,%6,%7}, {%8,%9}, {%0,%1,%2,%3};" \
        : "+f"(d0), "+f"(d1), "+f"(d2), "+f"(d3) \
        : "r"(aa0), "r"(aa1), "r"(aa2), "r"(aa3), "r"(bb0), "r"(bb1))

#define DECL_C(p) float p##0 = 0.f, p##1 = 0.f, p##2 = 0.f, p##3 = 0.f

// ---------------- exact median via dual-rank radix select on |w| bits -------
// nonnegative floats order identically to their uint32 bit patterns.
// Tracks BOTH middle order statistics (ranks n/2-1 and n/2) simultaneously.

__global__ void k_selinit2(unsigned n) {
    if (threadIdx.x == 0) {
        g_pre[0] = 0u; g_pre[1] = 0u;
        g_rank[0] = n / 2 - 1; g_rank[1] = n / 2;
    }
    for (int i = threadIdx.x; i < 512; i += blockDim.x)
        ((unsigned*)g_hist2)[i] = 0u;
}

__global__ void k_hist2(const float* __restrict__ w, unsigned n4, int level) {
    __shared__ unsigned sh[2][256];
    for (int i = threadIdx.x; i < 512; i += blockDim.x) ((unsigned*)sh)[i] = 0u;
    __syncthreads();
    const unsigned maskHigh = (level == 3) ? 0u : (0xFFFFFFFFu << ((level + 1) * 8));
    const unsigned p0 = g_pre[0] & maskHigh;
    const unsigned p1 = g_pre[1] & maskHigh;
    const bool same = (p0 == p1);
    const int shift = level * 8;
    const float4* w4 = (const float4*)w;
    for (unsigned i = blockIdx.x * blockDim.x + threadIdx.x; i < n4;
         i += gridDim.x * blockDim.x) {
        float4 v = w4[i];
        unsigned u0 = __float_as_uint(v.x) & 0x7FFFFFFFu;
        unsigned u1 = __float_as_uint(v.y) & 0x7FFFFFFFu;
        unsigned u2 = __float_as_uint(v.z) & 0x7FFFFFFFu;
        unsigned u3 = __float_as_uint(v.w) & 0x7FFFFFFFu;
        if ((u0 & maskHigh) == p0) atomicAdd(&sh[0][(u0 >> shift) & 255u], 1u);
        if ((u1 & maskHigh) == p0) atomicAdd(&sh[0][(u1 >> shift) & 255u], 1u);
        if ((u2 & maskHigh) == p0) atomicAdd(&sh[0][(u2 >> shift) & 255u], 1u);
        if ((u3 & maskHigh) == p0) atomicAdd(&sh[0][(u3 >> shift) & 255u], 1u);
        if (!same) {
            if ((u0 & maskHigh) == p1) atomicAdd(&sh[1][(u0 >> shift) & 255u], 1u);
            if ((u1 & maskHigh) == p1) atomicAdd(&sh[1][(u1 >> shift) & 255u], 1u);
            if ((u2 & maskHigh) == p1) atomicAdd(&sh[1][(u2 >> shift) & 255u], 1u);
            if ((u3 & maskHigh) == p1) atomicAdd(&sh[1][(u3 >> shift) & 255u], 1u);
        }
    }
    __syncthreads();
    for (int i = threadIdx.x; i < 256; i += blockDim.x) {
        if (sh[0][i]) atomicAdd(&g_hist2[0][i], sh[0][i]);
        if (sh[1][i]) atomicAdd(&g_hist2[1][i], sh[1][i]);
    }
}

__global__ void k_pick2(int level, int sidx) {
    const unsigned maskHigh = (level == 3) ? 0u : (0xFFFFFFFFu << ((level + 1) * 8));
    const bool same = ((g_pre[0] ^ g_pre[1]) & maskHigh) == 0u;
    for (int r = 0; r < 2; ++r) {
        const unsigned* h = (r == 1 && !same) ? g_hist2[1] : g_hist2[0];
        unsigned k = g_rank[r];
        unsigned cum = 0; int bsel = 0;
        for (int bi = 0; bi < 256; ++bi) {
            unsigned c = h[bi];
            if (cum + c > k) { bsel = bi; break; }
            cum += c;
        }
        g_pre[r] |= ((unsigned)bsel) << (level * 8);
        g_rank[r] = k - cum;
    }
    for (int i = 0; i < 256; ++i) { g_hist2[0][i] = 0u; g_hist2[1][i] = 0u; }
    if (level == 0) {
        // jnp.median for even n: mean of the two middle values
        float a = __uint_as_float(g_pre[0]);
        float b = __uint_as_float(g_pre[1]);
        g_sc[sidx] = fmaxf(0.5f * (a + b), 1e-8f);
    }
}

// ---------------- ternary quantization: codes {-1,0,+1} as fp16 (exact) -----
__global__ void k_quant(const float* __restrict__ w, unsigned n, int sidx, int which) {
    __half* q = (which == 0) ? g_w1q : g_w2q;
    const float s = g_sc[sidx];
    for (unsigned i = blockIdx.x * blockDim.x + threadIdx.x; i < n;
         i += gridDim.x * blockDim.x) {
        float t = rintf(w[i] / s);              // round-half-even == jnp.round
        t = fminf(fmaxf(t, -1.0f), 1.0f);
        q[i] = __float2half(t);
    }
}

// ---------------- x fp32 -> fp16 --------------------------------------------
__global__ void k_cvt(const float* __restrict__ x, unsigned n2) {
    __half2* o2 = (__half2*)g_xh;
    for (unsigned i = blockIdx.x * blockDim.x + threadIdx.x; i < n2;
         i += gridDim.x * blockDim.x) {
        float2 v = ((const float2*)x)[i];
        o2[i] = __floats2half2_rn(v.x, v.y);
    }
}

// ---------------- BN epilogue constants (scale s folded into multiplier) ----
__global__ void k_bnparams(const float* __restrict__ g, const float* __restrict__ b,
                           const float* __restrict__ m, const float* __restrict__ v,
                           int n, int sidx, int which) {
    float* A  = (which == 0) ? g_A1 : g_A2;
    float* Bc = (which == 0) ? g_B1 : g_B2;
    const float s = g_sc[sidx];
    int i = blockIdx.x * blockDim.x + threadIdx.x;
    if (i < n) {
        float inv = g[i] * __frsqrt_rn(v[i] + 1e-5f);
        A[i]  = inv * s;
        Bc[i] = b[i] - m[i] * inv;
    }
}

// ---------------- fused tensor-core GEMM + BN + SiLU ------------------------
// Per-batch GEMM: Out[b][m][n] = silu( (sum_k Wq[m][k] * X[b][k][n]) * A[m] + B[m] )
// mma.sync.m16n8k16 fp16/fp32-acc. Block tile 256x64, 8 warps as 4(M) x 2(N),
// warp tile 64x32. cp.async double buffer in DYNAMIC smem (50176 B > 48K static).

__device__ __forceinline__ float silu(float y) {
    return y / (1.0f + expf(-y));
}

extern __shared__ __align__(16) char dynsmem[];

template<int LAYER>
__global__ __launch_bounds__(256)
void k_gemm_mma(float* __restrict__ OutExt) {
    constexpr int K = (LAYER == 1) ? C1_ : KCAT;
    const __half* __restrict__ Wq = (LAYER == 1) ? g_w1q : g_w2q;
    const float* __restrict__ Ae = (LAYER == 1) ? g_A1  : g_A2;
    const float* __restrict__ Be = (LAYER == 1) ? g_B1  : g_B2;

    const int b   = blockIdx.z;
    const int n0  = blockIdx.x * BN;
    const int m0  = blockIdx.y * BM;
    const int tid = threadIdx.x;
    const int lane = tid & 31;
    const int wid  = tid >> 5;
    const int wm = wid >> 1;   // 0..3 : 64-row slice
    const int wn = wid & 1;    // 0..1 : 32-col slice

    typedef __half AsT[BM][BK + 8];
    typedef __half BsT[BK][BN + 8];
    AsT* As = reinterpret_cast<AsT*>(dynsmem);                          // [2]
    BsT* Bs = reinterpret_cast<BsT*>(dynsmem + 2 * sizeof(AsT));        // [2]

    // 64 named accumulators: c{mt}{nt}{i}, mt 0..3, nt 0..3
    DECL_C(c00); DECL_C(c01); DECL_C(c02); DECL_C(c03);
    DECL_C(c10); DECL_C(c11); DECL_C(c12); DECL_C(c13);
    DECL_C(c20); DECL_C(c21); DECL_C(c22); DECL_C(c23);
    DECL_C(c30); DECL_C(c31); DECL_C(c32); DECL_C(c33);

    // async copy mappings (all 16B chunks)
    const int ar  = tid >> 2;        // 0..63  (A rows, +64/+128/+192 passes)
    const int ac  = tid & 3;         // col chunk (8 halfs)
    const int br  = tid >> 3;        // 0..31  (B rows)
    const int bc  = tid & 7;         // col chunk

    auto issue = [&](int t, int s) {
        const int k0 = t * BK;
        cp16(&As[s][ar      ][ac * 8], Wq + (size_t)(m0 + ar      ) * K + k0 + ac * 8);
        cp16(&As[s][ar +  64][ac * 8], Wq + (size_t)(m0 + ar +  64) * K + k0 + ac * 8);
        cp16(&As[s][ar + 128][ac * 8], Wq + (size_t)(m0 + ar + 128) * K + k0 + ac * 8);
        cp16(&As[s][ar + 192][ac * 8], Wq + (size_t)(m0 + ar + 192) * K + k0 + ac * 8);
        const __half* src; size_t off;
        if (LAYER == 1) {
            src = g_xh;
            off = ((size_t)b * K + (k0 + br)) * HWp;
        } else {
            int kk = k0 + br;
            int si = kk >> 9, cc = kk & 511;
            src = (si == 0) ? g_h : (si == 1) ? g_y1 : (si == 2) ? g_y2 : g_y3;
            off = ((size_t)b * HID_ + cc) * HWp;
        }
        cp16(&Bs[s][br][bc * 8], src + off + n0 + bc * 8);
        cp_commit();
    };

    issue(0, 0);
    cp_wait0();
    __syncthreads();

    const int lr = lane & 15;        // ldmatrix row-select
    const int lc = (lane >> 4) * 8;  // ldmatrix col-half select

    constexpr int NT = K / BK;
    for (int t = 0; t < NT; ++t) {
        const int s = t & 1;
        if (t + 1 < NT) issue(t + 1, s ^ 1);
#pragma unroll
        for (int kk = 0; kk < 2; ++kk) {
            const int k16 = kk * 16;
            unsigned b00, b01, b02, b03, b10, b11, b12, b13;
            unsigned a0, a1, a2, a3;
            {
                unsigned ad = (unsigned)__cvta_generic_to_shared(
                    &Bs[s][k16 + lr][wn * 32 + lc]);
                LDSM4T(b00, b01, b02, b03, ad);
            }
            {
                unsigned ad = (unsigned)__cvta_generic_to_shared(
                    &Bs[s][k16 + lr][wn * 32 + 16 + lc]);
                LDSM4T(b10, b11, b12, b13, ad);
            }
#define MROW_STEP(mt)                                                          \
            {                                                                  \
                unsigned ad = (unsigned)__cvta_generic_to_shared(              \
                    &As[s][wm * 64 + (mt) * 16 + lr][k16 + lc]);               \
                LDSM4(a0, a1, a2, a3, ad);                                     \
            }                                                                  \
            MMA16816(c##mt##00, c##mt##01, c##mt##02, c##mt##03,               \
                     a0, a1, a2, a3, b00, b01);                                \
            MMA16816(c##mt##10, c##mt##11, c##mt##12, c##mt##13,               \
                     a0, a1, a2, a3, b02, b03);                                \
            MMA16816(c##mt##20, c##mt##21, c##mt##22, c##mt##23,               \
                     a0, a1, a2, a3, b10, b11);                                \
            MMA16816(c##mt##30, c##mt##31, c##mt##32, c##mt##33,               \
                     a0, a1, a2, a3, b12, b13)
            MROW_STEP(0);
            MROW_STEP(1);
            MROW_STEP(2);
            MROW_STEP(3);
#undef MROW_STEP
        }
        if (t + 1 < NT) cp_wait0();
        __syncthreads();
    }

    // epilogue: BN + SiLU (named scalars only)
#define STORE_TILE(cc, mtv, ntv) do {                                          \
        const int mrow = m0 + wm * 64 + (mtv) * 16 + (lane >> 2);              \
        const int col  = n0 + wn * 32 + (ntv) * 8 + (lane & 3) * 2;            \
        const float A0 = Ae[mrow],     Bv0 = Be[mrow];                         \
        const float A1 = Ae[mrow + 8], Bv1 = Be[mrow + 8];                     \
        float v0 = silu(cc##0 * A0 + Bv0), v1 = silu(cc##1 * A0 + Bv0);        \
        float v2 = silu(cc##2 * A1 + Bv1), v3 = silu(cc##3 * A1 + Bv1);        \
        if (LAYER == 1) {                                                      \
            *(__half2*)(g_h + ((size_t)b * HID_ + mrow) * HWp + col) =         \
                __floats2half2_rn(v0, v1);                                     \
            *(__half2*)(g_h + ((size_t)b * HID_ + mrow + 8) * HWp + col) =     \
                __floats2half2_rn(v2, v3);                                     \
        } else {                                                               \
            *(float2*)(OutExt + ((size_t)b * C2_ + mrow) * HWp + col) =        \
                make_float2(v0, v1);                                           \
            *(float2*)(OutExt + ((size_t)b * C2_ + mrow + 8) * HWp + col) =    \
                make_float2(v2, v3);                                           \
        }                                                                      \
    } while (0)

    STORE_TILE(c00, 0, 0); STORE_TILE(c01, 0, 1); STORE_TILE(c02, 0, 2); STORE_TILE(c03, 0, 3);
    STORE_TILE(c10, 1, 0); STORE_TILE(c11, 1, 1); STORE_TILE(c12, 1, 2); STORE_TILE(c13, 1, 3);
    STORE_TILE(c20, 2, 0); STORE_TILE(c21, 2, 1); STORE_TILE(c22, 2, 2); STORE_TILE(c23, 2, 3);
    STORE_TILE(c30, 3, 0); STORE_TILE(c31, 3, 1); STORE_TILE(c32, 3, 2); STORE_TILE(c33, 3, 3);
#undef STORE_TILE
}

// ---------------- 5x5 stride-1 pad-2 maxpool (separable, fp16) --------------
__global__ __launch_bounds__(256)
void k_pool(int stage) {
    const __half* in  = (stage == 0) ? g_h  : (stage == 1) ? g_y1 : g_y2;
    __half*       out = (stage == 0) ? g_y1 : (stage == 1) ? g_y2 : g_y3;

    __shared__ __half p[HWp];
    __shared__ __half tmp[HWp];
    const size_t plane = (size_t)blockIdx.x * HWp;
    const int tid = threadIdx.x;

    for (int i = tid; i < HWp; i += 256) p[i] = in[plane + i];
    __syncthreads();
    for (int i = tid; i < HWp; i += 256) {
        int y = i / 40, x = i % 40;
        __half m = p[i];
        int x0 = max(x - 2, 0), x1 = min(x + 2, 39);
        for (int xx = x0; xx <= x1; ++xx) m = __hmax(m, p[y * 40 + xx]);
        tmp[i] = m;
    }
    __syncthreads();
    for (int i = tid; i < HWp; i += 256) {
        int y = i / 40, x = i % 40;
        __half m = tmp[i];
        int y0 = max(y - 2, 0), y1 = min(y + 2, 39);
        for (int yy = y0; yy <= y1; ++yy) m = __hmax(m, tmp[yy * 40 + x]);
        out[plane + i] = m;
    }
}

// ---------------- host orchestration (all graph-capturable launches) --------
static void run_select2(const float* w, unsigned n, int sidx) {
    k_selinit2<<<1, 256>>>(n);
    for (int level = 3; level >= 0; --level) {
        k_hist2<<<512, 256>>>(w, n / 4, level);
        k_pick2<<<1, 1>>>(level, sidx);
    }
}

extern "C" void kernel_launch(void* const* d_in, const int* in_sizes, int n_in,
                              void* d_out, int out_size) {
    const float* x  = (const float*)d_in[0];
    const float* w1 = (const float*)d_in[1];
    const float* g1 = (const float*)d_in[2];
    const float* b1 = (const float*)d_in[3];
    const float* m1 = (const float*)d_in[4];
    const float* v1 = (const float*)d_in[5];
    const float* w2 = (const float*)d_in[6];
    const float* g2 = (const float*)d_in[7];
    const float* b2 = (const float*)d_in[8];
    const float* m2 = (const float*)d_in[9];
    const float* v2 = (const float*)d_in[10];
    float* out = (float*)d_out;

    // allow >48K dynamic smem for the GEMM kernels (host attr set, not an alloc;
    // idempotent and graph-capture-safe)
    cudaFuncSetAttribute(k_gemm_mma<1>, cudaFuncAttributeMaxDynamicSharedMemorySize, SMEM_GEMM);
    cudaFuncSetAttribute(k_gemm_mma<2>, cudaFuncAttributeMaxDynamicSharedMemorySize, SMEM_GEMM);

    // convert activations to fp16 (writes device symbol from device code)
    k_cvt<<<2048, 256>>>(x, (unsigned)((size_t)B_ * C1_ * HWp / 2));

    // exact medians (dual-rank radix select: both middle order statistics)
    run_select2(w1, N1, 0);
    run_select2(w2, N2, 1);

    // quantize weights to ternary fp16 codes
    k_quant<<<1024, 256>>>(w1, N1, 0, 0);
    k_quant<<<2048, 256>>>(w2, N2, 1, 1);

    // BN epilogue constants (fold s into multiplier)
    k_bnparams<<<(HID_ + 255) / 256, 256>>>(g1, b1, m1, v1, HID_, 0, 0);
    k_bnparams<<<(C2_  + 255) / 256, 256>>>(g2, b2, m2, v2, C2_,  1, 1);

    // layer 1: conv1x1 + BN + SiLU -> g_h (fp16)
    {
        dim3 grid(HWp / BN, HID_ / BM, B_);
        k_gemm_mma<1><<<grid, 256, SMEM_GEMM>>>(nullptr);
    }

    // cascaded 5x5 maxpools (fp16, exact)
    k_pool<<<B_ * HID_, 256>>>(0);
    k_pool<<<B_ * HID_, 256>>>(1);
    k_pool<<<B_ * HID_, 256>>>(2);

    // layer 2: conv1x1 over virtual concat + BN + SiLU -> out (fp32)
    {
        dim3 grid(HWp / BN, C2_ / BM, B_);
        k_gemm_mma<2><<<grid, 256, SMEM_GEMM>>>(out);
    }
}

// round 10
// speedup vs baseline: 4.2429x; 1.0307x over previous
#include <cuda_runtime.h>
#include <cuda_fp16.h>
#include <math.h>

// ---------------- problem constants ----------------
#define HWp   1600            // 40*40 pixels, contiguous innermost
#define B_    32
#define C1_   1024
#define HID_  512
#define C2_   1024
#define KCAT  2048
#define N1    (HID_*C1_)      // 524288  (w1 elements)
#define N2    (C2_*KCAT)      // 2097152 (w2 elements)

// GEMM tiling
#define BM 256
#define BN 64
#define BK 32
#define NSTAGE 4
#define SMEM_GEMM (NSTAGE*(BM*(BK+8) + BK*(BN+8))*2)   // 100352 bytes (dynamic)

// ---------------- scratch (device globals; no allocs allowed) ----------------
// NOTE: referenced ONLY from device code (host-side use of a __device__ symbol
// yields the host BSS shadow and trips HMM migration — rounds 2-6 bug).
__device__ __half g_xh[(size_t)B_*C1_*HWp];   // x in fp16
__device__ __half g_h [(size_t)B_*HID_*HWp];
__device__ __half g_y1[(size_t)B_*HID_*HWp];
__device__ __half g_y2[(size_t)B_*HID_*HWp];
__device__ __half g_y3[(size_t)B_*HID_*HWp];
__device__ __half g_w1q[N1];
__device__ __half g_w2q[N2];
__device__ float g_A1[HID_], g_B1[HID_];
__device__ float g_A2[C2_],  g_B2[C2_];
__device__ float g_sc[2];              // s1, s2 (median scales)
__device__ unsigned g_pre[2];          // dual-rank radix-select prefixes
__device__ unsigned g_rank[2];         // remaining ranks
__device__ unsigned g_hist2[2][256];

// ---------------- cp.async helpers ------------------------------------------
__device__ __forceinline__ void cp16(void* smem_dst, const void* gmem_src) {
    unsigned d = (unsigned)__cvta_generic_to_shared(smem_dst);
    asm volatile("cp.async.cg.shared.global [%0], [%1], 16;" :: "r"(d), "l"(gmem_src));
}
__device__ __forceinline__ void cp_commit() {
    asm volatile("cp.async.commit_group;");
}
template<int N>
__device__ __forceinline__ void cp_wait() {
    asm volatile("cp.async.wait_group %0;" :: "n"(N));
}

// ---------------- scalar-only mma / ldmatrix macros --------------------------
#define LDSM4(r0,r1,r2,r3,addr) \
    asm volatile("ldmatrix.sync.aligned.m8n8.x4.shared.b16 {%0,%1,%2,%3}, [%4];" \
        : "=r"(r0), "=r"(r1), "=r"(r2), "=r"(r3) : "r"(addr))

#define LDSM4T(r0,r1,r2,r3,addr) \
    asm volatile("ldmatrix.sync.aligned.m8n8.x4.trans.shared.b16 {%0,%1,%2,%3}, [%4];" \
        : "=r"(r0), "=r"(r1), "=r"(r2), "=r"(r3) : "r"(addr))

#define MMA16816(d0,d1,d2,d3,aa0,aa1,aa2,aa3,bb0,bb1) \
    asm volatile("mma.sync.aligned.m16n8k16.row.col.f32.f16.f16.f32 " \
        "{%0,%1,%2,%3}, {%4,%5,%6,%7}, {%8,%9}, {%0,%1,%2,%3};" \
        : "+f"(d0), "+f"(d1), "+f"(d2), "+f"(d3) \
        : "r"(aa0), "r"(aa1), "r"(aa2), "r"(aa3), "r"(bb0), "r"(bb1))

#define DECL_C(p) float p##0 = 0.f, p##1 = 0.f, p##2 = 0.f, p##3 = 0.f

// ---------------- exact median via dual-rank radix select on |w| bits -------
// nonnegative floats order identically to their uint32 bit patterns.
// Tracks BOTH middle order statistics (ranks n/2-1 and n/2) simultaneously.

__global__ void k_selinit2(unsigned n) {
    if (threadIdx.x == 0) {
        g_pre[0] = 0u; g_pre[1] = 0u;
        g_rank[0] = n / 2 - 1; g_rank[1] = n / 2;
    }
    for (int i = threadIdx.x; i < 512; i += blockDim.x)
        ((unsigned*)g_hist2)[i] = 0u;
}

__global__ void k_hist2(const float* __restrict__ w, unsigned n4, int level) {
    __shared__ unsigned sh[2][256];
    for (int i = threadIdx.x; i < 512; i += blockDim.x) ((unsigned*)sh)[i] = 0u;
    __syncthreads();
    const unsigned maskHigh = (level == 3) ? 0u : (0xFFFFFFFFu << ((level + 1) * 8));
    const unsigned p0 = g_pre[0] & maskHigh;
    const unsigned p1 = g_pre[1] & maskHigh;
    const bool same = (p0 == p1);
    const int shift = level * 8;
    const float4* w4 = (const float4*)w;
    for (unsigned i = blockIdx.x * blockDim.x + threadIdx.x; i < n4;
         i += gridDim.x * blockDim.x) {
        float4 v = w4[i];
        unsigned u0 = __float_as_uint(v.x) & 0x7FFFFFFFu;
        unsigned u1 = __float_as_uint(v.y) & 0x7FFFFFFFu;
        unsigned u2 = __float_as_uint(v.z) & 0x7FFFFFFFu;
        unsigned u3 = __float_as_uint(v.w) & 0x7FFFFFFFu;
        if ((u0 & maskHigh) == p0) atomicAdd(&sh[0][(u0 >> shift) & 255u], 1u);
        if ((u1 & maskHigh) == p0) atomicAdd(&sh[0][(u1 >> shift) & 255u], 1u);
        if ((u2 & maskHigh) == p0) atomicAdd(&sh[0][(u2 >> shift) & 255u], 1u);
        if ((u3 & maskHigh) == p0) atomicAdd(&sh[0][(u3 >> shift) & 255u], 1u);
        if (!same) {
            if ((u0 & maskHigh) == p1) atomicAdd(&sh[1][(u0 >> shift) & 255u], 1u);
            if ((u1 & maskHigh) == p1) atomicAdd(&sh[1][(u1 >> shift) & 255u], 1u);
            if ((u2 & maskHigh) == p1) atomicAdd(&sh[1][(u2 >> shift) & 255u], 1u);
            if ((u3 & maskHigh) == p1) atomicAdd(&sh[1][(u3 >> shift) & 255u], 1u);
        }
    }
    __syncthreads();
    for (int i = threadIdx.x; i < 256; i += blockDim.x) {
        if (sh[0][i]) atomicAdd(&g_hist2[0][i], sh[0][i]);
        if (sh[1][i]) atomicAdd(&g_hist2[1][i], sh[1][i]);
    }
}

// parallel pick: 256-thread inclusive scan over both histograms
__global__ void k_pick2(int level, int sidx) {
    __shared__ unsigned scan0[256], scan1[256];
    const int ti = threadIdx.x;
    const unsigned maskHigh = (level == 3) ? 0u : (0xFFFFFFFFu << ((level + 1) * 8));
    const bool same = ((g_pre[0] ^ g_pre[1]) & maskHigh) == 0u;
    // snapshot ranks BEFORE any writes (avoids read/write race)
    const unsigned k0 = g_rank[0];
    const unsigned k1 = g_rank[1];
    const unsigned c0 = g_hist2[0][ti];
    const unsigned c1 = same ? c0 : g_hist2[1][ti];
    scan0[ti] = c0; scan1[ti] = c1;
    __syncthreads();
    for (int off = 1; off < 256; off <<= 1) {
        unsigned v0 = (ti >= off) ? scan0[ti - off] : 0u;
        unsigned v1 = (ti >= off) ? scan1[ti - off] : 0u;
        __syncthreads();
        scan0[ti] += v0; scan1[ti] += v1;
        __syncthreads();
    }
    {   // rank 0 uses histogram 0
        unsigned incl = scan0[ti], excl = incl - c0;
        if (c0 && excl <= k0 && k0 < incl) {
            atomicOr(&g_pre[0], (unsigned)ti << (level * 8));
            g_rank[0] = k0 - excl;
        }
    }
    {   // rank 1 uses histogram 1 when prefixes diverged, else histogram 0
        unsigned incl = same ? scan0[ti] : scan1[ti];
        unsigned cc   = same ? c0 : c1;
        unsigned excl = incl - cc;
        if (cc && excl <= k1 && k1 < incl) {
            atomicOr(&g_pre[1], (unsigned)ti << (level * 8));
            g_rank[1] = k1 - excl;
        }
    }
    // clear hist for next level
    g_hist2[0][ti] = 0u; g_hist2[1][ti] = 0u;
    __syncthreads();
    if (level == 0 && ti == 0) {
        // jnp.median for even n: mean of the two middle values
        float a = __uint_as_float(g_pre[0]);
        float b = __uint_as_float(g_pre[1]);
        g_sc[sidx] = fmaxf(0.5f * (a + b), 1e-8f);
    }
}

// ---------------- ternary quantization: codes {-1,0,+1} as fp16 (exact) -----
__global__ void k_quant(const float* __restrict__ w, unsigned n, int sidx, int which) {
    __half* q = (which == 0) ? g_w1q : g_w2q;
    const float s = g_sc[sidx];
    for (unsigned i = blockIdx.x * blockDim.x + threadIdx.x; i < n;
         i += gridDim.x * blockDim.x) {
        float t = rintf(w[i] / s);              // round-half-even == jnp.round
        t = fminf(fmaxf(t, -1.0f), 1.0f);
        q[i] = __float2half(t);
    }
}

// ---------------- x fp32 -> fp16 --------------------------------------------
__global__ void k_cvt(const float* __restrict__ x, unsigned n2) {
    __half2* o2 = (__half2*)g_xh;
    for (unsigned i = blockIdx.x * blockDim.x + threadIdx.x; i < n2;
         i += gridDim.x * blockDim.x) {
        float2 v = ((const float2*)x)[i];
        o2[i] = __floats2half2_rn(v.x, v.y);
    }
}

// ---------------- BN epilogue constants (scale s folded into multiplier) ----
__global__ void k_bnparams(const float* __restrict__ g, const float* __restrict__ b,
                           const float* __restrict__ m, const float* __restrict__ v,
                           int n, int sidx, int which) {
    float* A  = (which == 0) ? g_A1 : g_A2;
    float* Bc = (which == 0) ? g_B1 : g_B2;
    const float s = g_sc[sidx];
    int i = blockIdx.x * blockDim.x + threadIdx.x;
    if (i < n) {
        float inv = g[i] * __frsqrt_rn(v[i] + 1e-5f);
        A[i]  = inv * s;
        Bc[i] = b[i] - m[i] * inv;
    }
}

// ---------------- fused tensor-core GEMM + BN + SiLU ------------------------
// Per-batch GEMM: Out[b][m][n] = silu( (sum_k Wq[m][k] * X[b][k][n]) * A[m] + B[m] )
// mma.sync.m16n8k16 fp16/fp32-acc. Block tile 256x64, 8 warps as 4(M) x 2(N),
// warp tile 64x32. 4-stage cp.async pipeline (wait_group 2) in dynamic smem.

__device__ __forceinline__ float silu(float y) {
    return y / (1.0f + expf(-y));
}

extern __shared__ __align__(16) char dynsmem[];

template<int LAYER>
__global__ __launch_bounds__(256)
void k_gemm_mma(float* __restrict__ OutExt) {
    constexpr int K = (LAYER == 1) ? C1_ : KCAT;
    const __half* __restrict__ Wq = (LAYER == 1) ? g_w1q : g_w2q;
    const float* __restrict__ Ae = (LAYER == 1) ? g_A1  : g_A2;
    const float* __restrict__ Be = (LAYER == 1) ? g_B1  : g_B2;

    const int b   = blockIdx.z;
    const int n0  = blockIdx.x * BN;
    const int m0  = blockIdx.y * BM;
    const int tid = threadIdx.x;
    const int lane = tid & 31;
    const int wid  = tid >> 5;
    const int wm = wid >> 1;   // 0..3 : 64-row slice
    const int wn = wid & 1;    // 0..1 : 32-col slice

    typedef __half AsT[BM][BK + 8];
    typedef __half BsT[BK][BN + 8];
    AsT* As = reinterpret_cast<AsT*>(dynsmem);                                // [NSTAGE]
    BsT* Bs = reinterpret_cast<BsT*>(dynsmem + NSTAGE * sizeof(AsT));         // [NSTAGE]

    // 64 named accumulators: c{mt}{nt}{i}, mt 0..3, nt 0..3
    DECL_C(c00); DECL_C(c01); DECL_C(c02); DECL_C(c03);
    DECL_C(c10); DECL_C(c11); DECL_C(c12); DECL_C(c13);
    DECL_C(c20); DECL_C(c21); DECL_C(c22); DECL_C(c23);
    DECL_C(c30); DECL_C(c31); DECL_C(c32); DECL_C(c33);

    // async copy mappings (all 16B chunks)
    const int ar  = tid >> 2;        // 0..63  (A rows, +64/+128/+192 passes)
    const int ac  = tid & 3;         // col chunk (8 halfs)
    const int br  = tid >> 3;        // 0..31  (B rows)
    const int bc  = tid & 7;         // col chunk

    auto issue = [&](int t, int s) {
        const int k0 = t * BK;
        cp16(&As[s][ar      ][ac * 8], Wq + (size_t)(m0 + ar      ) * K + k0 + ac * 8);
        cp16(&As[s][ar +  64][ac * 8], Wq + (size_t)(m0 + ar +  64) * K + k0 + ac * 8);
        cp16(&As[s][ar + 128][ac * 8], Wq + (size_t)(m0 + ar + 128) * K + k0 + ac * 8);
        cp16(&As[s][ar + 192][ac * 8], Wq + (size_t)(m0 + ar + 192) * K + k0 + ac * 8);
        const __half* src; size_t off;
        if (LAYER == 1) {
            src = g_xh;
            off = ((size_t)b * K + (k0 + br)) * HWp;
        } else {
            int kk = k0 + br;
            int si = kk >> 9, cc = kk & 511;
            src = (si == 0) ? g_h : (si == 1) ? g_y1 : (si == 2) ? g_y2 : g_y3;
            off = ((size_t)b * HID_ + cc) * HWp;
        }
        cp16(&Bs[s][br][bc * 8], src + off + n0 + bc * 8);
        cp_commit();
    };

    constexpr int NT = K / BK;
    // prologue: fill NSTAGE-1 stages
    issue(0, 0); issue(1, 1); issue(2, 2);

    const int lr = lane & 15;        // ldmatrix row-select
    const int lc = (lane >> 4) * 8;  // ldmatrix col-half select

    for (int t = 0; t < NT; ++t) {
        const int s = t & (NSTAGE - 1);
        cp_wait<NSTAGE - 2>();       // stage s complete
        __syncthreads();             // all warps done with stage being overwritten
        if (t + NSTAGE - 1 < NT) issue(t + NSTAGE - 1, (t + NSTAGE - 1) & (NSTAGE - 1));
#pragma unroll
        for (int kk = 0; kk < 2; ++kk) {
            const int k16 = kk * 16;
            unsigned b00, b01, b02, b03, b10, b11, b12, b13;
            unsigned a0, a1, a2, a3;
            {
                unsigned ad = (unsigned)__cvta_generic_to_shared(
                    &Bs[s][k16 + lr][wn * 32 + lc]);
                LDSM4T(b00, b01, b02, b03, ad);
            }
            {
                unsigned ad = (unsigned)__cvta_generic_to_shared(
                    &Bs[s][k16 + lr][wn * 32 + 16 + lc]);
                LDSM4T(b10, b11, b12, b13, ad);
            }
#define MROW_STEP(mt)                                                          \
            {                                                                  \
                unsigned ad = (unsigned)__cvta_generic_to_shared(              \
                    &As[s][wm * 64 + (mt) * 16 + lr][k16 + lc]);               \
                LDSM4(a0, a1, a2, a3, ad);                                     \
            }                                                                  \
            MMA16816(c##mt##00, c##mt##01, c##mt##02, c##mt##03,               \
                     a0, a1, a2, a3, b00, b01);                                \
            MMA16816(c##mt##10, c##mt##11, c##mt##12, c##mt##13,               \
                     a0, a1, a2, a3, b02, b03);                                \
            MMA16816(c##mt##20, c##mt##21, c##mt##22, c##mt##23,               \
                     a0, a1, a2, a3, b10, b11);                                \
            MMA16816(c##mt##30, c##mt##31, c##mt##32, c##mt##33,               \
                     a0, a1, a2, a3, b12, b13)
            MROW_STEP(0);
            MROW_STEP(1);
            MROW_STEP(2);
            MROW_STEP(3);
#undef MROW_STEP
        }
    }

    // epilogue: BN + SiLU (named scalars only)
#define STORE_TILE(cc, mtv, ntv) do {                                          \
        const int mrow = m0 + wm * 64 + (mtv) * 16 + (lane >> 2);              \
        const int col  = n0 + wn * 32 + (ntv) * 8 + (lane & 3) * 2;            \
        const float A0 = Ae[mrow],     Bv0 = Be[mrow];                         \
        const float A1 = Ae[mrow + 8], Bv1 = Be[mrow + 8];                     \
        float v0 = silu(cc##0 * A0 + Bv0), v1 = silu(cc##1 * A0 + Bv0);        \
        float v2 = silu(cc##2 * A1 + Bv1), v3 = silu(cc##3 * A1 + Bv1);        \
        if (LAYER == 1) {                                                      \
            *(__half2*)(g_h + ((size_t)b * HID_ + mrow) * HWp + col) =         \
                __floats2half2_rn(v0, v1);                                     \
            *(__half2*)(g_h + ((size_t)b * HID_ + mrow + 8) * HWp + col) =     \
                __floats2half2_rn(v2, v3);                                     \
        } else {                                                               \
            *(float2*)(OutExt + ((size_t)b * C2_ + mrow) * HWp + col) =        \
                make_float2(v0, v1);                                           \
            *(float2*)(OutExt + ((size_t)b * C2_ + mrow + 8) * HWp + col) =    \
                make_float2(v2, v3);                                           \
        }                                                                      \
    } while (0)

    STORE_TILE(c00, 0, 0); STORE_TILE(c01, 0, 1); STORE_TILE(c02, 0, 2); STORE_TILE(c03, 0, 3);
    STORE_TILE(c10, 1, 0); STORE_TILE(c11, 1, 1); STORE_TILE(c12, 1, 2); STORE_TILE(c13, 1, 3);
    STORE_TILE(c20, 2, 0); STORE_TILE(c21, 2, 1); STORE_TILE(c22, 2, 2); STORE_TILE(c23, 2, 3);
    STORE_TILE(c30, 3, 0); STORE_TILE(c31, 3, 1); STORE_TILE(c32, 3, 2); STORE_TILE(c33, 3, 3);
#undef STORE_TILE
}

// ---------------- 5x5 stride-1 pad-2 maxpool (separable, fp16) --------------
__global__ __launch_bounds__(256)
void k_pool(int stage) {
    const __half* in  = (stage == 0) ? g_h  : (stage == 1) ? g_y1 : g_y2;
    __half*       out = (stage == 0) ? g_y1 : (stage == 1) ? g_y2 : g_y3;

    __shared__ __half p[HWp];
    __shared__ __half tmp[HWp];
    const size_t plane = (size_t)blockIdx.x * HWp;
    const int tid = threadIdx.x;

    for (int i = tid; i < HWp; i += 256) p[i] = in[plane + i];
    __syncthreads();
    for (int i = tid; i < HWp; i += 256) {
        int y = i / 40, x = i % 40;
        __half m = p[i];
        int x0 = max(x - 2, 0), x1 = min(x + 2, 39);
        for (int xx = x0; xx <= x1; ++xx) m = __hmax(m, p[y * 40 + xx]);
        tmp[i] = m;
    }
    __syncthreads();
    for (int i = tid; i < HWp; i += 256) {
        int y = i / 40, x = i % 40;
        __half m = tmp[i];
        int y0 = max(y - 2, 0), y1 = min(y + 2, 39);
        for (int yy = y0; yy <= y1; ++yy) m = __hmax(m, tmp[yy * 40 + x]);
        out[plane + i] = m;
    }
}

// ---------------- host orchestration (all graph-capturable launches) --------
static void run_select2(const float* w, unsigned n, int sidx) {
    k_selinit2<<<1, 256>>>(n);
    for (int level = 3; level >= 0; --level) {
        k_hist2<<<512, 256>>>(w, n / 4, level);
        k_pick2<<<1, 256>>>(level, sidx);
    }
}

extern "C" void kernel_launch(void* const* d_in, const int* in_sizes, int n_in,
                              void* d_out, int out_size) {
    const float* x  = (const float*)d_in[0];
    const float* w1 = (const float*)d_in[1];
    const float* g1 = (const float*)d_in[2];
    const float* b1 = (const float*)d_in[3];
    const float* m1 = (const float*)d_in[4];
    const float* v1 = (const float*)d_in[5];
    const float* w2 = (const float*)d_in[6];
    const float* g2 = (const float*)d_in[7];
    const float* b2 = (const float*)d_in[8];
    const float* m2 = (const float*)d_in[9];
    const float* v2 = (const float*)d_in[10];
    float* out = (float*)d_out;

    // allow >48K dynamic smem for the GEMM kernels (host attr set, not an alloc;
    // idempotent and graph-capture-safe)
    cudaFuncSetAttribute(k_gemm_mma<1>, cudaFuncAttributeMaxDynamicSharedMemorySize, SMEM_GEMM);
    cudaFuncSetAttribute(k_gemm_mma<2>, cudaFuncAttributeMaxDynamicSharedMemorySize, SMEM_GEMM);

    // convert activations to fp16 (writes device symbol from device code)
    k_cvt<<<2048, 256>>>(x, (unsigned)((size_t)B_ * C1_ * HWp / 2));

    // exact medians (dual-rank radix select: both middle order statistics)
    run_select2(w1, N1, 0);
    run_select2(w2, N2, 1);

    // quantize weights to ternary fp16 codes
    k_quant<<<1024, 256>>>(w1, N1, 0, 0);
    k_quant<<<2048, 256>>>(w2, N2, 1, 1);

    // BN epilogue constants (fold s into multiplier)
    k_bnparams<<<(HID_ + 255) / 256, 256>>>(g1, b1, m1, v1, HID_, 0, 0);
    k_bnparams<<<(C2_  + 255) / 256, 256>>>(g2, b2, m2, v2, C2_,  1, 1);

    // layer 1: conv1x1 + BN + SiLU -> g_h (fp16)
    {
        dim3 grid(HWp / BN, HID_ / BM, B_);
        k_gemm_mma<1><<<grid, 256, SMEM_GEMM>>>(nullptr);
    }

    // cascaded 5x5 maxpools (fp16, exact)
    k_pool<<<B_ * HID_, 256>>>(0);
    k_pool<<<B_ * HID_, 256>>>(1);
    k_pool<<<B_ * HID_, 256>>>(2);

    // layer 2: conv1x1 over virtual concat + BN + SiLU -> out (fp32)
    {
        dim3 grid(HWp / BN, C2_ / BM, B_);
        k_gemm_mma<2><<<grid, 256, SMEM_GEMM>>>(out);
    }
}

// round 14
// speedup vs baseline: 4.4967x; 1.0598x over previous
#include <cuda_runtime.h>
#include <cuda_fp16.h>
#include <cstdint>
#include <math.h>

// ---------------- problem constants ----------------
#define HWp   1600            // 40*40 pixels, contiguous innermost
#define B_    32
#define C1_   1024
#define HID_  512
#define C2_   1024
#define KCAT  2048
#define N1    (HID_*C1_)      // 524288  (w1 elements)
#define N2    (C2_*KCAT)      // 2097152 (w2 elements)

// GEMM tiling
#define BM 256
#define BN 64
#define BK 32
#define NSTAGE 4
#define SMEM_GEMM (NSTAGE*(BM*(BK+8) + BK*(BN+8))*2)   // 100352 bytes (dynamic)

// ---------------- scratch (device globals; no allocs allowed) ----------------
// NOTE: referenced ONLY from device code (host-side use of a __device__ symbol
// yields the host BSS shadow and trips HMM migration — rounds 2-6 bug).
__device__ __half g_xh[(size_t)B_*C1_*HWp];   // x in fp16
__device__ __half g_h [(size_t)B_*HID_*HWp];
__device__ __half g_y1[(size_t)B_*HID_*HWp];
__device__ __half g_y2[(size_t)B_*HID_*HWp];
__device__ __half g_y3[(size_t)B_*HID_*HWp];
__device__ __half g_w1q[N1];
__device__ __half g_w2q[N2];
__device__ float g_A1[HID_], g_B1[HID_];
__device__ float g_A2[C2_],  g_B2[C2_];
__device__ float g_sc[2];              // s1, s2 (median scales)
__device__ unsigned g_pre[2];          // dual-rank radix-select prefixes
__device__ unsigned g_rank[2];         // remaining ranks
__device__ unsigned g_hist2[2][256];

// ---------------- cp.async helpers ------------------------------------------
__device__ __forceinline__ void cp16(void* smem_dst, const void* gmem_src) {
    unsigned d = (unsigned)__cvta_generic_to_shared(smem_dst);
    asm volatile("cp.async.cg.shared.global [%0], [%1], 16;" :: "r"(d), "l"(gmem_src));
}
__device__ __forceinline__ void cp_commit() {
    asm volatile("cp.async.commit_group;");
}
template<int N>
__device__ __forceinline__ void cp_wait() {
    asm volatile("cp.async.wait_group %0;" :: "n"(N));
}

// ---------------- scalar-only mma / ldmatrix macros --------------------------
#define LDSM4(r0,r1,r2,r3,addr) \
    asm volatile("ldmatrix.sync.aligned.m8n8.x4.shared.b16 {%0,%1,%2,%3}, [%4];" \
        : "=r"(r0), "=r"(r1), "=r"(r2), "=r"(r3) : "r"(addr))

#define LDSM4T(r0,r1,r2,r3,addr) \
    asm volatile("ldmatrix.sync.aligned.m8n8.x4.trans.shared.b16 {%0,%1,%2,%3}, [%4];" \
        : "=r"(r0), "=r"(r1), "=r"(r2), "=r"(r3) : "r"(addr))

#define MMA16816(d0,d1,d2,d3,aa0,aa1,aa2,aa3,bb0,bb1) \
    asm volatile("mma.sync.aligned.m16n8k16.row.col.f32.f16.f16.f32 " \
        "{%0,%1,%2,%3}, {%4,%5,%6,%7}, {%8,%9}, {%0,%1,%2,%3};" \
        : "+f"(d0), "+f"(d1), "+f"(d2), "+f"(d3) \
        : "r"(aa0), "r"(aa1), "r"(aa2), "r"(aa3), "r"(bb0), "r"(bb1))

#define DECL_C(p) float p##0 = 0.f, p##1 = 0.f, p##2 = 0.f, p##3 = 0.f
#define DECL_AF(g,mt) unsigned a##g##mt##0, a##g##mt##1, a##g##mt##2, a##g##mt##3
#define DECL_BF(g) unsigned b##g##0, b##g##1, b##g##2, b##g##3, \
                            b##g##4, b##g##5, b##g##6, b##g##7

// Load all fragments for k16-group g at column offset k16 (6 ldmatrix.x4)
#define LOADG(g, k16)                                                          \
    { unsigned ad = (unsigned)__cvta_generic_to_shared(                        \
          &Bs[s][(k16) + lr][wn * 32 + lc]);                                   \
      LDSM4T(b##g##0, b##g##1, b##g##2, b##g##3, ad); }                        \
    { unsigned ad = (unsigned)__cvta_generic_to_shared(                        \
          &Bs[s][(k16) + lr][wn * 32 + 16 + lc]);                              \
      LDSM4T(b##g##4, b##g##5, b##g##6, b##g##7, ad); }                        \
    { unsigned ad = (unsigned)__cvta_generic_to_shared(                        \
          &As[s][wm * 64 +  0 + lr][(k16) + lc]);                              \
      LDSM4(a##g##00, a##g##01, a##g##02, a##g##03, ad); }                     \
    { unsigned ad = (unsigned)__cvta_generic_to_shared(                        \
          &As[s][wm * 64 + 16 + lr][(k16) + lc]);                              \
      LDSM4(a##g##10, a##g##11, a##g##12, a##g##13, ad); }                     \
    { unsigned ad = (unsigned)__cvta_generic_to_shared(                        \
          &As[s][wm * 64 + 32 + lr][(k16) + lc]);                              \
      LDSM4(a##g##20, a##g##21, a##g##22, a##g##23, ad); }                     \
    { unsigned ad = (unsigned)__cvta_generic_to_shared(                        \
          &As[s][wm * 64 + 48 + lr][(k16) + lc]);                              \
      LDSM4(a##g##30, a##g##31, a##g##32, a##g##33, ad); }

// 16 MMAs for group g, m-subtile mt
#define MROWX(g, mt)                                                           \
    MMA16816(c##mt##00, c##mt##01, c##mt##02, c##mt##03,                       \
             a##g##mt##0, a##g##mt##1, a##g##mt##2, a##g##mt##3,               \
             b##g##0, b##g##1);                                                \
    MMA16816(c##mt##10, c##mt##11, c##mt##12, c##mt##13,                       \
             a##g##mt##0, a##g##mt##1, a##g##mt##2, a##g##mt##3,               \
             b##g##2, b##g##3);                                                \
    MMA16816(c##mt##20, c##mt##21, c##mt##22, c##mt##23,                       \
             a##g##mt##0, a##g##mt##1, a##g##mt##2, a##g##mt##3,               \
             b##g##4, b##g##5);                                                \
    MMA16816(c##mt##30, c##mt##31, c##mt##32, c##mt##33,                       \
             a##g##mt##0, a##g##mt##1, a##g##mt##2, a##g##mt##3,               \
             b##g##6, b##g##7)

#define MMAG(g) MROWX(g, 0); MROWX(g, 1); MROWX(g, 2); MROWX(g, 3)

// ---------------- exact median via dual-rank radix select on |w| bits -------
__global__ void k_selinit2(unsigned n) {
    if (threadIdx.x == 0) {
        g_pre[0] = 0u; g_pre[1] = 0u;
        g_rank[0] = n / 2 - 1; g_rank[1] = n / 2;
    }
    for (int i = threadIdx.x; i < 512; i += blockDim.x)
        ((unsigned*)g_hist2)[i] = 0u;
}

__global__ void k_hist2(const float* __restrict__ w, unsigned n4, int level) {
    __shared__ unsigned sh[2][256];
    for (int i = threadIdx.x; i < 512; i += blockDim.x) ((unsigned*)sh)[i] = 0u;
    __syncthreads();
    const unsigned maskHigh = (level == 3) ? 0u : (0xFFFFFFFFu << ((level + 1) * 8));
    const unsigned p0 = g_pre[0] & maskHigh;
    const unsigned p1 = g_pre[1] & maskHigh;
    const bool same = (p0 == p1);
    const int shift = level * 8;
    const float4* w4 = (const float4*)w;
    for (unsigned i = blockIdx.x * blockDim.x + threadIdx.x; i < n4;
         i += gridDim.x * blockDim.x) {
        float4 v = w4[i];
        unsigned u0 = __float_as_uint(v.x) & 0x7FFFFFFFu;
        unsigned u1 = __float_as_uint(v.y) & 0x7FFFFFFFu;
        unsigned u2 = __float_as_uint(v.z) & 0x7FFFFFFFu;
        unsigned u3 = __float_as_uint(v.w) & 0x7FFFFFFFu;
        if ((u0 & maskHigh) == p0) atomicAdd(&sh[0][(u0 >> shift) & 255u], 1u);
        if ((u1 & maskHigh) == p0) atomicAdd(&sh[0][(u1 >> shift) & 255u], 1u);
        if ((u2 & maskHigh) == p0) atomicAdd(&sh[0][(u2 >> shift) & 255u], 1u);
        if ((u3 & maskHigh) == p0) atomicAdd(&sh[0][(u3 >> shift) & 255u], 1u);
        if (!same) {
            if ((u0 & maskHigh) == p1) atomicAdd(&sh[1][(u0 >> shift) & 255u], 1u);
            if ((u1 & maskHigh) == p1) atomicAdd(&sh[1][(u1 >> shift) & 255u], 1u);
            if ((u2 & maskHigh) == p1) atomicAdd(&sh[1][(u2 >> shift) & 255u], 1u);
            if ((u3 & maskHigh) == p1) atomicAdd(&sh[1][(u3 >> shift) & 255u], 1u);
        }
    }
    __syncthreads();
    for (int i = threadIdx.x; i < 256; i += blockDim.x) {
        if (sh[0][i]) atomicAdd(&g_hist2[0][i], sh[0][i]);
        if (sh[1][i]) atomicAdd(&g_hist2[1][i], sh[1][i]);
    }
}

// parallel pick: 256-thread inclusive scan over both histograms
__global__ void k_pick2(int level, int sidx) {
    __shared__ unsigned scan0[256], scan1[256];
    const int ti = threadIdx.x;
    const unsigned maskHigh = (level == 3) ? 0u : (0xFFFFFFFFu << ((level + 1) * 8));
    const bool same = ((g_pre[0] ^ g_pre[1]) & maskHigh) == 0u;
    const unsigned k0 = g_rank[0];
    const unsigned k1 = g_rank[1];
    const unsigned c0 = g_hist2[0][ti];
    const unsigned c1 = same ? c0 : g_hist2[1][ti];
    scan0[ti] = c0; scan1[ti] = c1;
    __syncthreads();
    for (int off = 1; off < 256; off <<= 1) {
        unsigned v0 = (ti >= off) ? scan0[ti - off] : 0u;
        unsigned v1 = (ti >= off) ? scan1[ti - off] : 0u;
        __syncthreads();
        scan0[ti] += v0; scan1[ti] += v1;
        __syncthreads();
    }
    {
        unsigned incl = scan0[ti], excl = incl - c0;
        if (c0 && excl <= k0 && k0 < incl) {
            atomicOr(&g_pre[0], (unsigned)ti << (level * 8));
            g_rank[0] = k0 - excl;
        }
    }
    {
        unsigned incl = same ? scan0[ti] : scan1[ti];
        unsigned cc   = same ? c0 : c1;
        unsigned excl = incl - cc;
        if (cc && excl <= k1 && k1 < incl) {
            atomicOr(&g_pre[1], (unsigned)ti << (level * 8));
            g_rank[1] = k1 - excl;
        }
    }
    g_hist2[0][ti] = 0u; g_hist2[1][ti] = 0u;
    __syncthreads();
    if (level == 0 && ti == 0) {
        float a = __uint_as_float(g_pre[0]);
        float b = __uint_as_float(g_pre[1]);
        g_sc[sidx] = fmaxf(0.5f * (a + b), 1e-8f);
    }
}

// ---------------- ternary quantization: codes {-1,0,+1} as fp16 (exact) -----
__global__ void k_quant(const float* __restrict__ w, unsigned n, int sidx, int which) {
    __half* q = (which == 0) ? g_w1q : g_w2q;
    const float s = g_sc[sidx];
    for (unsigned i = blockIdx.x * blockDim.x + threadIdx.x; i < n;
         i += gridDim.x * blockDim.x) {
        float t = rintf(w[i] / s);              // round-half-even == jnp.round
        t = fminf(fmaxf(t, -1.0f), 1.0f);
        q[i] = __float2half(t);
    }
}

// ---------------- x fp32 -> fp16 --------------------------------------------
__global__ void k_cvt(const float* __restrict__ x, unsigned n2) {
    __half2* o2 = (__half2*)g_xh;
    for (unsigned i = blockIdx.x * blockDim.x + threadIdx.x; i < n2;
         i += gridDim.x * blockDim.x) {
        float2 v = ((const float2*)x)[i];
        o2[i] = __floats2half2_rn(v.x, v.y);
    }
}

// ---------------- BN epilogue constants (scale s folded into multiplier) ----
__global__ void k_bnparams(const float* __restrict__ g, const float* __restrict__ b,
                           const float* __restrict__ m, const float* __restrict__ v,
                           int n, int sidx, int which) {
    float* A  = (which == 0) ? g_A1 : g_A2;
    float* Bc = (which == 0) ? g_B1 : g_B2;
    const float s = g_sc[sidx];
    int i = blockIdx.x * blockDim.x + threadIdx.x;
    if (i < n) {
        float inv = g[i] * __frsqrt_rn(v[i] + 1e-5f);
        A[i]  = inv * s;
        Bc[i] = b[i] - m[i] * inv;
    }
}

// ---------------- fused tensor-core GEMM + BN + SiLU ------------------------
// mma.sync.m16n8k16 fp16/fp32-acc. Block tile 256x64, 8 warps as 4(M) x 2(N),
// warp tile 64x32. 4-stage cp.async pipeline. Both k16 groups' fragments are
// loaded up-front (named scalars) so ldmatrix latency hides under MMA issue.

__device__ __forceinline__ float silu(float y) {
    return y / (1.0f + expf(-y));
}

extern __shared__ __align__(16) char dynsmem[];

template<int LAYER>
__global__ __launch_bounds__(256)
void k_gemm_mma(float* __restrict__ OutExt) {
    constexpr int K = (LAYER == 1) ? C1_ : KCAT;
    const __half* __restrict__ Wq = (LAYER == 1) ? g_w1q : g_w2q;
    const float* __restrict__ Ae = (LAYER == 1) ? g_A1  : g_A2;
    const float* __restrict__ Be = (LAYER == 1) ? g_B1  : g_B2;

    const int b   = blockIdx.z;
    const int n0  = blockIdx.x * BN;
    const int m0  = blockIdx.y * BM;
    const int tid = threadIdx.x;
    const int lane = tid & 31;
    const int wid  = tid >> 5;
    const int wm = wid >> 1;   // 0..3 : 64-row slice
    const int wn = wid & 1;    // 0..1 : 32-col slice

    typedef __half AsT[BM][BK + 8];
    typedef __half BsT[BK][BN + 8];
    AsT* As = reinterpret_cast<AsT*>(dynsmem);                                // [NSTAGE]
    BsT* Bs = reinterpret_cast<BsT*>(dynsmem + NSTAGE * sizeof(AsT));         // [NSTAGE]

    // 64 named accumulators
    DECL_C(c00); DECL_C(c01); DECL_C(c02); DECL_C(c03);
    DECL_C(c10); DECL_C(c11); DECL_C(c12); DECL_C(c13);
    DECL_C(c20); DECL_C(c21); DECL_C(c22); DECL_C(c23);
    DECL_C(c30); DECL_C(c31); DECL_C(c32); DECL_C(c33);
    // fragment double buffer (named scalars)
    DECL_BF(0); DECL_BF(1);
    DECL_AF(0,0); DECL_AF(0,1); DECL_AF(0,2); DECL_AF(0,3);
    DECL_AF(1,0); DECL_AF(1,1); DECL_AF(1,2); DECL_AF(1,3);

    // async copy mappings (all 16B chunks)
    const int ar  = tid >> 2;        // 0..63  (A rows, +64/+128/+192 passes)
    const int ac  = tid & 3;
    const int br  = tid >> 3;        // 0..31  (B rows)
    const int bc  = tid & 7;

    auto issue = [&](int t, int s) {
        const int k0 = t * BK;
        cp16(&As[s][ar      ][ac * 8], Wq + (size_t)(m0 + ar      ) * K + k0 + ac * 8);
        cp16(&As[s][ar +  64][ac * 8], Wq + (size_t)(m0 + ar +  64) * K + k0 + ac * 8);
        cp16(&As[s][ar + 128][ac * 8], Wq + (size_t)(m0 + ar + 128) * K + k0 + ac * 8);
        cp16(&As[s][ar + 192][ac * 8], Wq + (size_t)(m0 + ar + 192) * K + k0 + ac * 8);
        const __half* src; size_t off;
        if (LAYER == 1) {
            src = g_xh;
            off = ((size_t)b * K + (k0 + br)) * HWp;
        } else {
            int kk = k0 + br;
            int si = kk >> 9, cc = kk & 511;
            src = (si == 0) ? g_h : (si == 1) ? g_y1 : (si == 2) ? g_y2 : g_y3;
            off = ((size_t)b * HID_ + cc) * HWp;
        }
        cp16(&Bs[s][br][bc * 8], src + off + n0 + bc * 8);
        cp_commit();
    };

    constexpr int NT = K / BK;
    issue(0, 0); issue(1, 1); issue(2, 2);

    const int lr = lane & 15;
    const int lc = (lane >> 4) * 8;

    for (int t = 0; t < NT; ++t) {
        const int s = t & (NSTAGE - 1);
        // tail-aware wait: guarantee group t's loads have landed
        if (t < NT - 2)       cp_wait<2>();
        else if (t == NT - 2) cp_wait<1>();
        else                  cp_wait<0>();
        __syncthreads();
        if (t + NSTAGE - 1 < NT) issue(t + NSTAGE - 1, (t + NSTAGE - 1) & (NSTAGE - 1));

        // load ALL fragments for both k16 groups, then run all MMAs
        LOADG(0, 0)
        LOADG(1, 16)
        MMAG(0);
        MMAG(1);
    }

    // epilogue: BN + SiLU (named scalars only)
#define STORE_TILE(cc, mtv, ntv) do {                                          \
        const int mrow = m0 + wm * 64 + (mtv) * 16 + (lane >> 2);              \
        const int col  = n0 + wn * 32 + (ntv) * 8 + (lane & 3) * 2;            \
        const float A0 = Ae[mrow],     Bv0 = Be[mrow];                         \
        const float A1 = Ae[mrow + 8], Bv1 = Be[mrow + 8];                     \
        float v0 = silu(cc##0 * A0 + Bv0), v1 = silu(cc##1 * A0 + Bv0);        \
        float v2 = silu(cc##2 * A1 + Bv1), v3 = silu(cc##3 * A1 + Bv1);        \
        if (LAYER == 1) {                                                      \
            *(__half2*)(g_h + ((size_t)b * HID_ + mrow) * HWp + col) =         \
                __floats2half2_rn(v0, v1);                                     \
            *(__half2*)(g_h + ((size_t)b * HID_ + mrow + 8) * HWp + col) =     \
                __floats2half2_rn(v2, v3);                                     \
        } else {                                                               \
            *(float2*)(OutExt + ((size_t)b * C2_ + mrow) * HWp + col) =        \
                make_float2(v0, v1);                                           \
            *(float2*)(OutExt + ((size_t)b * C2_ + mrow + 8) * HWp + col) =    \
                make_float2(v2, v3);                                           \
        }                                                                      \
    } while (0)

    STORE_TILE(c00, 0, 0); STORE_TILE(c01, 0, 1); STORE_TILE(c02, 0, 2); STORE_TILE(c03, 0, 3);
    STORE_TILE(c10, 1, 0); STORE_TILE(c11, 1, 1); STORE_TILE(c12, 1, 2); STORE_TILE(c13, 1, 3);
    STORE_TILE(c20, 2, 0); STORE_TILE(c21, 2, 1); STORE_TILE(c22, 2, 2); STORE_TILE(c23, 2, 3);
    STORE_TILE(c30, 3, 0); STORE_TILE(c31, 3, 1); STORE_TILE(c32, 3, 2); STORE_TILE(c33, 3, 3);
#undef STORE_TILE
}

// ---------------- 5x5 stride-1 pad-2 maxpool (separable, fp16) --------------
__global__ __launch_bounds__(256)
void k_pool(int stage) {
    const __half* in  = (stage == 0) ? g_h  : (stage == 1) ? g_y1 : g_y2;
    __half*       out = (stage == 0) ? g_y1 : (stage == 1) ? g_y2 : g_y3;

    __shared__ __half p[HWp];
    __shared__ __half tmp[HWp];
    const size_t plane = (size_t)blockIdx.x * HWp;
    const int tid = threadIdx.x;

    for (int i = tid; i < HWp; i += 256) p[i] = in[plane + i];
    __syncthreads();
    for (int i = tid; i < HWp; i += 256) {
        int y = i / 40, x = i % 40;
        __half m = p[i];
        int x0 = max(x - 2, 0), x1 = min(x + 2, 39);
        for (int xx = x0; xx <= x1; ++xx) m = __hmax(m, p[y * 40 + xx]);
        tmp[i] = m;
    }
    __syncthreads();
    for (int i = tid; i < HWp; i += 256) {
        int y = i / 40, x = i % 40;
        __half m = tmp[i];
        int y0 = max(y - 2, 0), y1 = min(y + 2, 39);
        for (int yy = y0; yy <= y1; ++yy) m = __hmax(m, tmp[yy * 40 + x]);
        out[plane + i] = m;
    }
}

// ---------------- host orchestration (all graph-capturable launches) --------
static void run_select2(const float* w, unsigned n, int sidx) {
    k_selinit2<<<1, 256>>>(n);
    for (int level = 3; level >= 0; --level) {
        k_hist2<<<512, 256>>>(w, n / 4, level);
        k_pick2<<<1, 256>>>(level, sidx);
    }
}

extern "C" void kernel_launch(void* const* d_in, const int* in_sizes, int n_in,
                              void* d_out, int out_size) {
    const float* x  = (const float*)d_in[0];
    const float* w1 = (const float*)d_in[1];
    const float* g1 = (const float*)d_in[2];
    const float* b1 = (const float*)d_in[3];
    const float* m1 = (const float*)d_in[4];
    const float* v1 = (const float*)d_in[5];
    const float* w2 = (const float*)d_in[6];
    const float* g2 = (const float*)d_in[7];
    const float* b2 = (const float*)d_in[8];
    const float* m2 = (const float*)d_in[9];
    const float* v2 = (const float*)d_in[10];
    float* out = (float*)d_out;

    // allow >48K dynamic smem (host attr; idempotent, graph-capture-safe)
    cudaFuncSetAttribute(k_gemm_mma<1>, cudaFuncAttributeMaxDynamicSharedMemorySize, SMEM_GEMM);
    cudaFuncSetAttribute(k_gemm_mma<2>, cudaFuncAttributeMaxDynamicSharedMemorySize, SMEM_GEMM);

    // convert activations to fp16
    k_cvt<<<2048, 256>>>(x, (unsigned)((size_t)B_ * C1_ * HWp / 2));

    // exact medians (dual-rank radix select)
    run_select2(w1, N1, 0);
    run_select2(w2, N2, 1);

    // quantize weights to ternary fp16 codes
    k_quant<<<1024, 256>>>(w1, N1, 0, 0);
    k_quant<<<2048, 256>>>(w2, N2, 1, 1);

    // BN epilogue constants (fold s into multiplier)
    k_bnparams<<<(HID_ + 255) / 256, 256>>>(g1, b1, m1, v1, HID_, 0, 0);
    k_bnparams<<<(C2_  + 255) / 256, 256>>>(g2, b2, m2, v2, C2_,  1, 1);

    // layer 1: conv1x1 + BN + SiLU -> g_h (fp16)
    {
        dim3 grid(HWp / BN, HID_ / BM, B_);
        k_gemm_mma<1><<<grid, 256, SMEM_GEMM>>>(nullptr);
    }

    // cascaded 5x5 maxpools (fp16, exact)
    k_pool<<<B_ * HID_, 256>>>(0);
    k_pool<<<B_ * HID_, 256>>>(1);
    k_pool<<<B_ * HID_, 256>>>(2);

    // layer 2: conv1x1 over virtual concat + BN + SiLU -> out (fp32)
    {
        dim3 grid(HWp / BN, C2_ / BM, B_);
        k_gemm_mma<2><<<grid, 256, SMEM_GEMM>>>(out);
    }
}

// round 16
// speedup vs baseline: 4.5497x; 1.0118x over previous
#include <cuda_runtime.h>
#include <cuda_fp16.h>
#include <cstdint>
#include <math.h>

// ---------------- problem constants ----------------
#define HWp   1600            // 40*40 pixels, contiguous innermost
#define B_    32
#define C1_   1024
#define HID_  512
#define C2_   1024
#define KCAT  2048
#define N1    (HID_*C1_)      // 524288  (w1 elements)
#define N2    (C2_*KCAT)      // 2097152 (w2 elements)

// GEMM tiling
#define BM 256
#define BN 64
#define BK 32
#define NSTAGE 4
#define SMEM_GEMM (NSTAGE*(BM*(BK+8) + BK*(BN+8))*2)   // 100352 bytes (dynamic)

// ---------------- scratch (device globals; no allocs allowed) ----------------
// NOTE: referenced ONLY from device code (host-side use of a __device__ symbol
// yields the host BSS shadow and trips HMM migration — rounds 2-6 bug).
__device__ __half g_xh[(size_t)B_*C1_*HWp];   // x in fp16
__device__ __half g_h [(size_t)B_*HID_*HWp];
__device__ __half g_y1[(size_t)B_*HID_*HWp];
__device__ __half g_y2[(size_t)B_*HID_*HWp];
__device__ __half g_y3[(size_t)B_*HID_*HWp];
__device__ __half g_w1q[N1];
__device__ __half g_w2q[N2];
__device__ float g_A1[HID_], g_B1[HID_];
__device__ float g_A2[C2_],  g_B2[C2_];
__device__ float g_sc[2];              // s1, s2 (median scales)
__device__ unsigned g_pre[4];          // 4-way radix-select prefixes (2 tensors x 2 ranks)
__device__ unsigned g_rank[4];         // remaining ranks
__device__ unsigned g_hist4[4][256];

// ---------------- cp.async helpers ------------------------------------------
__device__ __forceinline__ void cp16(void* smem_dst, const void* gmem_src) {
    unsigned d = (unsigned)__cvta_generic_to_shared(smem_dst);
    asm volatile("cp.async.cg.shared.global [%0], [%1], 16;" :: "r"(d), "l"(gmem_src));
}
__device__ __forceinline__ void cp_commit() {
    asm volatile("cp.async.commit_group;");
}
template<int N>
__device__ __forceinline__ void cp_wait() {
    asm volatile("cp.async.wait_group %0;" :: "n"(N));
}

// ---------------- scalar-only mma / ldmatrix macros --------------------------
#define LDSM4(r0,r1,r2,r3,addr) \
    asm volatile("ldmatrix.sync.aligned.m8n8.x4.shared.b16 {%0,%1,%2,%3}, [%4];" \
        : "=r"(r0), "=r"(r1), "=r"(r2), "=r"(r3) : "r"(addr))

#define LDSM4T(r0,r1,r2,r3,addr) \
    asm volatile("ldmatrix.sync.aligned.m8n8.x4.trans.shared.b16 {%0,%1,%2,%3}, [%4];" \
        : "=r"(r0), "=r"(r1), "=r"(r2), "=r"(r3) : "r"(addr))

#define MMA16816(d0,d1,d2,d3,aa0,aa1,aa2,aa3,bb0,bb1) \
    asm volatile("mma.sync.aligned.m16n8k16.row.col.f32.f16.f16.f32 " \
        "{%0,%1,%2,%3}, {%4,%5,%6,%7}, {%8,%9}, {%0,%1,%2,%3};" \
        : "+f"(d0), "+f"(d1), "+f"(d2), "+f"(d3) \
        : "r"(aa0), "r"(aa1), "r"(aa2), "r"(aa3), "r"(bb0), "r"(bb1))

#define DECL_C(p) float p##0 = 0.f, p##1 = 0.f, p##2 = 0.f, p##3 = 0.f
#define DECL_AF(g,mt) unsigned a##g##mt##0, a##g##mt##1, a##g##mt##2, a##g##mt##3
#define DECL_BF(g) unsigned b##g##0, b##g##1, b##g##2, b##g##3, \
                            b##g##4, b##g##5, b##g##6, b##g##7

// Load all fragments for k16-group g at column offset k16 (6 ldmatrix.x4)
#define LOADG(g, k16)                                                          \
    { unsigned ad = (unsigned)__cvta_generic_to_shared(                        \
          &Bs[s][(k16) + lr][wn * 32 + lc]);                                   \
      LDSM4T(b##g##0, b##g##1, b##g##2, b##g##3, ad); }                        \
    { unsigned ad = (unsigned)__cvta_generic_to_shared(                        \
          &Bs[s][(k16) + lr][wn * 32 + 16 + lc]);                              \
      LDSM4T(b##g##4, b##g##5, b##g##6, b##g##7, ad); }                        \
    { unsigned ad = (unsigned)__cvta_generic_to_shared(                        \
          &As[s][wm * 64 +  0 + lr][(k16) + lc]);                              \
      LDSM4(a##g##00, a##g##01, a##g##02, a##g##03, ad); }                     \
    { unsigned ad = (unsigned)__cvta_generic_to_shared(                        \
          &As[s][wm * 64 + 16 + lr][(k16) + lc]);                              \
      LDSM4(a##g##10, a##g##11, a##g##12, a##g##13, ad); }                     \
    { unsigned ad = (unsigned)__cvta_generic_to_shared(                        \
          &As[s][wm * 64 + 32 + lr][(k16) + lc]);                              \
      LDSM4(a##g##20, a##g##21, a##g##22, a##g##23, ad); }                     \
    { unsigned ad = (unsigned)__cvta_generic_to_shared(                        \
          &As[s][wm * 64 + 48 + lr][(k16) + lc]);                              \
      LDSM4(a##g##30, a##g##31, a##g##32, a##g##33, ad); }

// 16 MMAs for group g, m-subtile mt
#define MROWX(g, mt)                                                           \
    MMA16816(c##mt##00, c##mt##01, c##mt##02, c##mt##03,                       \
             a##g##mt##0, a##g##mt##1, a##g##mt##2, a##g##mt##3,               \
             b##g##0, b##g##1);                                                \
    MMA16816(c##mt##10, c##mt##11, c##mt##12, c##mt##13,                       \
             a##g##mt##0, a##g##mt##1, a##g##mt##2, a##g##mt##3,               \
             b##g##2, b##g##3);                                                \
    MMA16816(c##mt##20, c##mt##21, c##mt##22, c##mt##23,                       \
             a##g##mt##0, a##g##mt##1, a##g##mt##2, a##g##mt##3,               \
             b##g##4, b##g##5);                                                \
    MMA16816(c##mt##30, c##mt##31, c##mt##32, c##mt##33,                       \
             a##g##mt##0, a##g##mt##1, a##g##mt##2, a##g##mt##3,               \
             b##g##6, b##g##7)

#define MMAG(g) MROWX(g, 0); MROWX(g, 1); MROWX(g, 2); MROWX(g, 3)

// ---------------- exact median: 4-way radix select (2 tensors x 2 ranks) ----
// nonnegative floats order identically to their uint32 bit patterns.

__global__ void k_selinit4() {
    if (threadIdx.x == 0) {
        g_pre[0] = 0u; g_pre[1] = 0u; g_pre[2] = 0u; g_pre[3] = 0u;
        g_rank[0] = N1 / 2 - 1; g_rank[1] = N1 / 2;
        g_rank[2] = N2 / 2 - 1; g_rank[3] = N2 / 2;
    }
    for (int i = threadIdx.x; i < 1024; i += blockDim.x)
        ((unsigned*)g_hist4)[i] = 0u;
}

__global__ void k_hist4(const float* __restrict__ w1, const float* __restrict__ w2,
                        int level) {
    __shared__ unsigned sh[4][256];
    for (int i = threadIdx.x; i < 1024; i += blockDim.x) ((unsigned*)sh)[i] = 0u;
    __syncthreads();
    const unsigned maskHigh = (level == 3) ? 0u : (0xFFFFFFFFu << ((level + 1) * 8));
    const int shift = level * 8;
#pragma unroll
    for (int ti = 0; ti < 2; ++ti) {
        const float4* w4 = (const float4*)(ti == 0 ? w1 : w2);
        const unsigned n4 = (ti == 0 ? N1 : N2) / 4;
        const unsigned p0 = g_pre[2 * ti]     & maskHigh;
        const unsigned p1 = g_pre[2 * ti + 1] & maskHigh;
        const bool same = (p0 == p1);
        unsigned* h0 = sh[2 * ti];
        unsigned* h1 = sh[2 * ti + 1];
        for (unsigned i = blockIdx.x * blockDim.x + threadIdx.x; i < n4;
             i += gridDim.x * blockDim.x) {
            float4 v = w4[i];
            unsigned u0 = __float_as_uint(v.x) & 0x7FFFFFFFu;
            unsigned u1 = __float_as_uint(v.y) & 0x7FFFFFFFu;
            unsigned u2 = __float_as_uint(v.z) & 0x7FFFFFFFu;
            unsigned u3 = __float_as_uint(v.w) & 0x7FFFFFFFu;
            if ((u0 & maskHigh) == p0) atomicAdd(&h0[(u0 >> shift) & 255u], 1u);
            if ((u1 & maskHigh) == p0) atomicAdd(&h0[(u1 >> shift) & 255u], 1u);
            if ((u2 & maskHigh) == p0) atomicAdd(&h0[(u2 >> shift) & 255u], 1u);
            if ((u3 & maskHigh) == p0) atomicAdd(&h0[(u3 >> shift) & 255u], 1u);
            if (!same) {
                if ((u0 & maskHigh) == p1) atomicAdd(&h1[(u0 >> shift) & 255u], 1u);
                if ((u1 & maskHigh) == p1) atomicAdd(&h1[(u1 >> shift) & 255u], 1u);
                if ((u2 & maskHigh) == p1) atomicAdd(&h1[(u2 >> shift) & 255u], 1u);
                if ((u3 & maskHigh) == p1) atomicAdd(&h1[(u3 >> shift) & 255u], 1u);
            }
        }
    }
    __syncthreads();
    for (int i = threadIdx.x; i < 256; i += blockDim.x) {
#pragma unroll
        for (int r = 0; r < 4; ++r)
            if (sh[r][i]) atomicAdd(&g_hist4[r][i], sh[r][i]);
    }
}

// parallel pick: 256-thread scan over 4 histograms
__global__ void k_pick4(int level) {
    __shared__ unsigned scans[4][256];
    const int ti = threadIdx.x;
    const unsigned maskHigh = (level == 3) ? 0u : (0xFFFFFFFFu << ((level + 1) * 8));
    const bool same0 = ((g_pre[0] ^ g_pre[1]) & maskHigh) == 0u;
    const bool same1 = ((g_pre[2] ^ g_pre[3]) & maskHigh) == 0u;
    unsigned kk0 = g_rank[0], kk1 = g_rank[1], kk2 = g_rank[2], kk3 = g_rank[3];
    const unsigned c0 = g_hist4[0][ti];
    const unsigned c1 = same0 ? c0 : g_hist4[1][ti];
    const unsigned c2 = g_hist4[2][ti];
    const unsigned c3 = same1 ? c2 : g_hist4[3][ti];
    scans[0][ti] = c0; scans[1][ti] = c1; scans[2][ti] = c2; scans[3][ti] = c3;
    __syncthreads();
    for (int off = 1; off < 256; off <<= 1) {
        unsigned v0 = (ti >= off) ? scans[0][ti - off] : 0u;
        unsigned v1 = (ti >= off) ? scans[1][ti - off] : 0u;
        unsigned v2 = (ti >= off) ? scans[2][ti - off] : 0u;
        unsigned v3 = (ti >= off) ? scans[3][ti - off] : 0u;
        __syncthreads();
        scans[0][ti] += v0; scans[1][ti] += v1;
        scans[2][ti] += v2; scans[3][ti] += v3;
        __syncthreads();
    }
#define PICK1(r, cc, sidx)                                                     \
    { unsigned incl = scans[sidx][ti], excl = incl - (cc);                     \
      unsigned kr = (r == 0) ? kk0 : (r == 1) ? kk1 : (r == 2) ? kk2 : kk3;    \
      if ((cc) && excl <= kr && kr < incl) {                                   \
          atomicOr(&g_pre[r], (unsigned)ti << (level * 8));                    \
          g_rank[r] = kr - excl;                                               \
      } }
    PICK1(0, c0, 0)
    PICK1(1, c1, (same0 ? 0 : 1))
    PICK1(2, c2, 2)
    PICK1(3, c3, (same1 ? 2 : 3))
#undef PICK1
#pragma unroll
    for (int r = 0; r < 4; ++r) g_hist4[r][ti] = 0u;
    __syncthreads();
    if (level == 0 && ti == 0) {
        g_sc[0] = fmaxf(0.5f * (__uint_as_float(g_pre[0]) + __uint_as_float(g_pre[1])), 1e-8f);
        g_sc[1] = fmaxf(0.5f * (__uint_as_float(g_pre[2]) + __uint_as_float(g_pre[3])), 1e-8f);
    }
}

// ---------------- ternary quantization: codes {-1,0,+1} as fp16 (exact) -----
__global__ void k_quant(const float* __restrict__ w, unsigned n, int sidx, int which) {
    __half* q = (which == 0) ? g_w1q : g_w2q;
    const float s = g_sc[sidx];
    for (unsigned i = blockIdx.x * blockDim.x + threadIdx.x; i < n;
         i += gridDim.x * blockDim.x) {
        float t = rintf(w[i] / s);              // round-half-even == jnp.round
        t = fminf(fmaxf(t, -1.0f), 1.0f);
        q[i] = __float2half(t);
    }
}

// ---------------- x fp32 -> fp16 --------------------------------------------
__global__ void k_cvt(const float* __restrict__ x, unsigned n2) {
    __half2* o2 = (__half2*)g_xh;
    for (unsigned i = blockIdx.x * blockDim.x + threadIdx.x; i < n2;
         i += gridDim.x * blockDim.x) {
        float2 v = ((const float2*)x)[i];
        o2[i] = __floats2half2_rn(v.x, v.y);
    }
}

// ---------------- BN epilogue constants (scale s folded into multiplier) ----
__global__ void k_bnparams(const float* __restrict__ g, const float* __restrict__ b,
                           const float* __restrict__ m, const float* __restrict__ v,
                           int n, int sidx, int which) {
    float* A  = (which == 0) ? g_A1 : g_A2;
    float* Bc = (which == 0) ? g_B1 : g_B2;
    const float s = g_sc[sidx];
    int i = blockIdx.x * blockDim.x + threadIdx.x;
    if (i < n) {
        float inv = g[i] * __frsqrt_rn(v[i] + 1e-5f);
        A[i]  = inv * s;
        Bc[i] = b[i] - m[i] * inv;
    }
}

// ---------------- fused tensor-core GEMM + BN + SiLU ------------------------
// mma.sync.m16n8k16 fp16/fp32-acc. Block tile 256x64, 8 warps as 4(M) x 2(N),
// warp tile 64x32. 4-stage cp.async pipeline (R14-verified structure: one
// chunk per wait+sync; issue targets the stage freed two iterations ago).

__device__ __forceinline__ float silu(float y) {
    return y / (1.0f + expf(-y));
}

extern __shared__ __align__(16) char dynsmem[];

template<int LAYER>
__global__ __launch_bounds__(256)
void k_gemm_mma(float* __restrict__ OutExt) {
    constexpr int K = (LAYER == 1) ? C1_ : KCAT;
    const __half* __restrict__ Wq = (LAYER == 1) ? g_w1q : g_w2q;
    const float* __restrict__ Ae = (LAYER == 1) ? g_A1  : g_A2;
    const float* __restrict__ Be = (LAYER == 1) ? g_B1  : g_B2;

    const int b   = blockIdx.z;
    const int n0  = blockIdx.x * BN;
    const int m0  = blockIdx.y * BM;
    const int tid = threadIdx.x;
    const int lane = tid & 31;
    const int wid  = tid >> 5;
    const int wm = wid >> 1;   // 0..3 : 64-row slice
    const int wn = wid & 1;    // 0..1 : 32-col slice

    typedef __half AsT[BM][BK + 8];
    typedef __half BsT[BK][BN + 8];
    AsT* As = reinterpret_cast<AsT*>(dynsmem);                                // [NSTAGE]
    BsT* Bs = reinterpret_cast<BsT*>(dynsmem + NSTAGE * sizeof(AsT));         // [NSTAGE]

    // 64 named accumulators
    DECL_C(c00); DECL_C(c01); DECL_C(c02); DECL_C(c03);
    DECL_C(c10); DECL_C(c11); DECL_C(c12); DECL_C(c13);
    DECL_C(c20); DECL_C(c21); DECL_C(c22); DECL_C(c23);
    DECL_C(c30); DECL_C(c31); DECL_C(c32); DECL_C(c33);
    // fragment regs (named scalars)
    DECL_BF(0); DECL_BF(1);
    DECL_AF(0,0); DECL_AF(0,1); DECL_AF(0,2); DECL_AF(0,3);
    DECL_AF(1,0); DECL_AF(1,1); DECL_AF(1,2); DECL_AF(1,3);

    // async copy mappings (all 16B chunks)
    const int ar  = tid >> 2;        // 0..63  (A rows, +64/+128/+192 passes)
    const int ac  = tid & 3;
    const int br  = tid >> 3;        // 0..31  (B rows)
    const int bc  = tid & 7;

    auto issue = [&](int t, int s) {
        const int k0 = t * BK;
        cp16(&As[s][ar      ][ac * 8], Wq + (size_t)(m0 + ar      ) * K + k0 + ac * 8);
        cp16(&As[s][ar +  64][ac * 8], Wq + (size_t)(m0 + ar +  64) * K + k0 + ac * 8);
        cp16(&As[s][ar + 128][ac * 8], Wq + (size_t)(m0 + ar + 128) * K + k0 + ac * 8);
        cp16(&As[s][ar + 192][ac * 8], Wq + (size_t)(m0 + ar + 192) * K + k0 + ac * 8);
        const __half* src; size_t off;
        if (LAYER == 1) {
            src = g_xh;
            off = ((size_t)b * K + (k0 + br)) * HWp;
        } else {
            int kk = k0 + br;
            int si = kk >> 9, cc = kk & 511;
            src = (si == 0) ? g_h : (si == 1) ? g_y1 : (si == 2) ? g_y2 : g_y3;
            off = ((size_t)b * HID_ + cc) * HWp;
        }
        cp16(&Bs[s][br][bc * 8], src + off + n0 + bc * 8);
        cp_commit();
    };

    constexpr int NT = K / BK;
    issue(0, 0); issue(1, 1); issue(2, 2);

    const int lr = lane & 15;
    const int lc = (lane >> 4) * 8;

    for (int t = 0; t < NT; ++t) {
        const int s = t & (NSTAGE - 1);
        // tail-aware wait: guarantee chunk t's loads have landed
        if (t < NT - 2)       cp_wait<2>();
        else if (t == NT - 2) cp_wait<1>();
        else                  cp_wait<0>();
        __syncthreads();
        if (t + NSTAGE - 1 < NT) issue(t + NSTAGE - 1, (t + NSTAGE - 1) & (NSTAGE - 1));

        // load ALL fragments for both k16 groups, then run all MMAs
        LOADG(0, 0)
        LOADG(1, 16)
        MMAG(0);
        MMAG(1);
    }

    // epilogue: BN + SiLU (named scalars only)
#define STORE_TILE(cc, mtv, ntv) do {                                          \
        const int mrow = m0 + wm * 64 + (mtv) * 16 + (lane >> 2);              \
        const int col  = n0 + wn * 32 + (ntv) * 8 + (lane & 3) * 2;            \
        const float A0 = Ae[mrow],     Bv0 = Be[mrow];                         \
        const float A1 = Ae[mrow + 8], Bv1 = Be[mrow + 8];                     \
        float v0 = silu(cc##0 * A0 + Bv0), v1 = silu(cc##1 * A0 + Bv0);        \
        float v2 = silu(cc##2 * A1 + Bv1), v3 = silu(cc##3 * A1 + Bv1);        \
        if (LAYER == 1) {                                                      \
            *(__half2*)(g_h + ((size_t)b * HID_ + mrow) * HWp + col) =         \
                __floats2half2_rn(v0, v1);                                     \
            *(__half2*)(g_h + ((size_t)b * HID_ + mrow + 8) * HWp + col) =     \
                __floats2half2_rn(v2, v3);                                     \
        } else {                                                               \
            *(float2*)(OutExt + ((size_t)b * C2_ + mrow) * HWp + col) =        \
                make_float2(v0, v1);                                           \
            *(float2*)(OutExt + ((size_t)b * C2_ + mrow + 8) * HWp + col) =    \
                make_float2(v2, v3);                                           \
        }                                                                      \
    } while (0)

    STORE_TILE(c00, 0, 0); STORE_TILE(c01, 0, 1); STORE_TILE(c02, 0, 2); STORE_TILE(c03, 0, 3);
    STORE_TILE(c10, 1, 0); STORE_TILE(c11, 1, 1); STORE_TILE(c12, 1, 2); STORE_TILE(c13, 1, 3);
    STORE_TILE(c20, 2, 0); STORE_TILE(c21, 2, 1); STORE_TILE(c22, 2, 2); STORE_TILE(c23, 2, 3);
    STORE_TILE(c30, 3, 0); STORE_TILE(c31, 3, 1); STORE_TILE(c32, 3, 2); STORE_TILE(c33, 3, 3);
#undef STORE_TILE
}

// ---------------- 5x5 stride-1 pad-2 maxpool (separable, fp16) --------------
__global__ __launch_bounds__(256)
void k_pool(int stage) {
    const __half* in  = (stage == 0) ? g_h  : (stage == 1) ? g_y1 : g_y2;
    __half*       out = (stage == 0) ? g_y1 : (stage == 1) ? g_y2 : g_y3;

    __shared__ __half p[HWp];
    __shared__ __half tmp[HWp];
    const size_t plane = (size_t)blockIdx.x * HWp;
    const int tid = threadIdx.x;

    for (int i = tid; i < HWp; i += 256) p[i] = in[plane + i];
    __syncthreads();
    for (int i = tid; i < HWp; i += 256) {
        int y = i / 40, x = i % 40;
        __half m = p[i];
        int x0 = max(x - 2, 0), x1 = min(x + 2, 39);
        for (int xx = x0; xx <= x1; ++xx) m = __hmax(m, p[y * 40 + xx]);
        tmp[i] = m;
    }
    __syncthreads();
    for (int i = tid; i < HWp; i += 256) {
        int y = i / 40, x = i % 40;
        __half m = tmp[i];
        int y0 = max(y - 2, 0), y1 = min(y + 2, 39);
        for (int yy = y0; yy <= y1; ++yy) m = __hmax(m, tmp[yy * 40 + x]);
        out[plane + i] = m;
    }
}

// ---------------- host orchestration (all graph-capturable launches) --------
extern "C" void kernel_launch(void* const* d_in, const int* in_sizes, int n_in,
                              void* d_out, int out_size) {
    const float* x  = (const float*)d_in[0];
    const float* w1 = (const float*)d_in[1];
    const float* g1 = (const float*)d_in[2];
    const float* b1 = (const float*)d_in[3];
    const float* m1 = (const float*)d_in[4];
    const float* v1 = (const float*)d_in[5];
    const float* w2 = (const float*)d_in[6];
    const float* g2 = (const float*)d_in[7];
    const float* b2 = (const float*)d_in[8];
    const float* m2 = (const float*)d_in[9];
    const float* v2 = (const float*)d_in[10];
    float* out = (float*)d_out;

    // allow >48K dynamic smem (host attr; idempotent, graph-capture-safe)
    cudaFuncSetAttribute(k_gemm_mma<1>, cudaFuncAttributeMaxDynamicSharedMemorySize, SMEM_GEMM);
    cudaFuncSetAttribute(k_gemm_mma<2>, cudaFuncAttributeMaxDynamicSharedMemorySize, SMEM_GEMM);

    // convert activations to fp16
    k_cvt<<<2048, 256>>>(x, (unsigned)((size_t)B_ * C1_ * HWp / 2));

    // exact medians: BOTH tensors in one 4-way radix-select sequence
    k_selinit4<<<1, 256>>>();
    for (int level = 3; level >= 0; --level) {
        k_hist4<<<512, 256>>>(w1, w2, level);
        k_pick4<<<1, 256>>>(level);
    }

    // quantize weights to ternary fp16 codes
    k_quant<<<1024, 256>>>(w1, N1, 0, 0);
    k_quant<<<2048, 256>>>(w2, N2, 1, 1);

    // BN epilogue constants (fold s into multiplier)
    k_bnparams<<<(HID_ + 255) / 256, 256>>>(g1, b1, m1, v1, HID_, 0, 0);
    k_bnparams<<<(C2_  + 255) / 256, 256>>>(g2, b2, m2, v2, C2_,  1, 1);

    // layer 1: conv1x1 + BN + SiLU -> g_h (fp16)
    {
        dim3 grid(HWp / BN, HID_ / BM, B_);
        k_gemm_mma<1><<<grid, 256, SMEM_GEMM>>>(nullptr);
    }

    // cascaded 5x5 maxpools (fp16, exact)
    k_pool<<<B_ * HID_, 256>>>(0);
    k_pool<<<B_ * HID_, 256>>>(1);
    k_pool<<<B_ * HID_, 256>>>(2);

    // layer 2: conv1x1 over virtual concat + BN + SiLU -> out (fp32)
    {
        dim3 grid(HWp / BN, C2_ / BM, B_);
        k_gemm_mma<2><<<grid, 256, SMEM_GEMM>>>(out);
    }
}

// round 17
// speedup vs baseline: 4.6590x; 1.0240x over previous
#include <cuda_runtime.h>
#include <cuda_fp16.h>
#include <cstdint>
#include <math.h>

// ---------------- problem constants ----------------
#define HWp   1600            // 40*40 pixels, contiguous innermost
#define B_    32
#define C1_   1024
#define HID_  512
#define C2_   1024
#define KCAT  2048
#define N1    (HID_*C1_)      // 524288  (w1 elements)
#define N2    (C2_*KCAT)      // 2097152 (w2 elements)

// GEMM tiling
#define BM 256
#define BN 64
#define BK 32
#define NSTAGE 4
#define SMEM_GEMM (NSTAGE*(BM*(BK+8) + BK*(BN+8))*2)   // 100352 bytes (dynamic)

// ---------------- scratch (device globals; no allocs allowed) ----------------
// NOTE: referenced ONLY from device code (host-side use of a __device__ symbol
// yields the host BSS shadow and trips HMM migration — rounds 2-6 bug).
__device__ __half g_xh[(size_t)B_*C1_*HWp];   // x in fp16
__device__ __half g_h [(size_t)B_*HID_*HWp];
__device__ __half g_y1[(size_t)B_*HID_*HWp];
__device__ __half g_y2[(size_t)B_*HID_*HWp];
__device__ __half g_y3[(size_t)B_*HID_*HWp];
__device__ __half g_w1q[N1];
__device__ __half g_w2q[N2];
__device__ float g_A1[HID_], g_B1[HID_];
__device__ float g_A2[C2_],  g_B2[C2_];
__device__ float g_sc[2];              // s1, s2 (median scales)
__device__ unsigned g_pre[4];          // 4-way radix-select prefixes (2 tensors x 2 ranks)
__device__ unsigned g_rank[4];         // remaining ranks
__device__ unsigned g_hist4[4][256];

// ---------------- cp.async helpers ------------------------------------------
__device__ __forceinline__ void cp16(void* smem_dst, const void* gmem_src) {
    unsigned d = (unsigned)__cvta_generic_to_shared(smem_dst);
    asm volatile("cp.async.cg.shared.global [%0], [%1], 16;" :: "r"(d), "l"(gmem_src));
}
__device__ __forceinline__ void cp_commit() {
    asm volatile("cp.async.commit_group;");
}
template<int N>
__device__ __forceinline__ void cp_wait() {
    asm volatile("cp.async.wait_group %0;" :: "n"(N));
}

// ---------------- scalar-only mma / ldmatrix macros --------------------------
#define LDSM4(r0,r1,r2,r3,addr) \
    asm volatile("ldmatrix.sync.aligned.m8n8.x4.shared.b16 {%0,%1,%2,%3}, [%4];" \
        : "=r"(r0), "=r"(r1), "=r"(r2), "=r"(r3) : "r"(addr))

#define LDSM4T(r0,r1,r2,r3,addr) \
    asm volatile("ldmatrix.sync.aligned.m8n8.x4.trans.shared.b16 {%0,%1,%2,%3}, [%4];" \
        : "=r"(r0), "=r"(r1), "=r"(r2), "=r"(r3) : "r"(addr))

#define MMA16816(d0,d1,d2,d3,aa0,aa1,aa2,aa3,bb0,bb1) \
    asm volatile("mma.sync.aligned.m16n8k16.row.col.f32.f16.f16.f32 " \
        "{%0,%1,%2,%3}, {%4,%5,%6,%7}, {%8,%9}, {%0,%1,%2,%3};" \
        : "+f"(d0), "+f"(d1), "+f"(d2), "+f"(d3) \
        : "r"(aa0), "r"(aa1), "r"(aa2), "r"(aa3), "r"(bb0), "r"(bb1))

#define DECL_C(p) float p##0 = 0.f, p##1 = 0.f, p##2 = 0.f, p##3 = 0.f
#define DECL_AF(g,mt) unsigned a##g##mt##0, a##g##mt##1, a##g##mt##2, a##g##mt##3
#define DECL_BF(g) unsigned b##g##0, b##g##1, b##g##2, b##g##3, \
                            b##g##4, b##g##5, b##g##6, b##g##7

// Load all fragments for k16-group g at column offset k16 (6 ldmatrix.x4)
#define LOADG(g, k16)                                                          \
    { unsigned ad = (unsigned)__cvta_generic_to_shared(                        \
          &Bs[s][(k16) + lr][wn * 32 + lc]);                                   \
      LDSM4T(b##g##0, b##g##1, b##g##2, b##g##3, ad); }                        \
    { unsigned ad = (unsigned)__cvta_generic_to_shared(                        \
          &Bs[s][(k16) + lr][wn * 32 + 16 + lc]);                              \
      LDSM4T(b##g##4, b##g##5, b##g##6, b##g##7, ad); }                        \
    { unsigned ad = (unsigned)__cvta_generic_to_shared(                        \
          &As[s][wm * 64 +  0 + lr][(k16) + lc]);                              \
      LDSM4(a##g##00, a##g##01, a##g##02, a##g##03, ad); }                     \
    { unsigned ad = (unsigned)__cvta_generic_to_shared(                        \
          &As[s][wm * 64 + 16 + lr][(k16) + lc]);                              \
      LDSM4(a##g##10, a##g##11, a##g##12, a##g##13, ad); }                     \
    { unsigned ad = (unsigned)__cvta_generic_to_shared(                        \
          &As[s][wm * 64 + 32 + lr][(k16) + lc]);                              \
      LDSM4(a##g##20, a##g##21, a##g##22, a##g##23, ad); }                     \
    { unsigned ad = (unsigned)__cvta_generic_to_shared(                        \
          &As[s][wm * 64 + 48 + lr][(k16) + lc]);                              \
      LDSM4(a##g##30, a##g##31, a##g##32, a##g##33, ad); }

// 16 MMAs for group g, m-subtile mt
#define MROWX(g, mt)                                                           \
    MMA16816(c##mt##00, c##mt##01, c##mt##02, c##mt##03,                       \
             a##g##mt##0, a##g##mt##1, a##g##mt##2, a##g##mt##3,               \
             b##g##0, b##g##1);                                                \
    MMA16816(c##mt##10, c##mt##11, c##mt##12, c##mt##13,                       \
             a##g##mt##0, a##g##mt##1, a##g##mt##2, a##g##mt##3,               \
             b##g##2, b##g##3);                                                \
    MMA16816(c##mt##20, c##mt##21, c##mt##22, c##mt##23,                       \
             a##g##mt##0, a##g##mt##1, a##g##mt##2, a##g##mt##3,               \
             b##g##4, b##g##5);                                                \
    MMA16816(c##mt##30, c##mt##31, c##mt##32, c##mt##33,                       \
             a##g##mt##0, a##g##mt##1, a##g##mt##2, a##g##mt##3,               \
             b##g##6, b##g##7)

#define MMAG(g) MROWX(g, 0); MROWX(g, 1); MROWX(g, 2); MROWX(g, 3)

// ---------------- exact median: 4-way radix select (2 tensors x 2 ranks) ----
// nonnegative floats order identically to their uint32 bit patterns.

__global__ void k_selinit4() {
    if (threadIdx.x == 0) {
        g_pre[0] = 0u; g_pre[1] = 0u; g_pre[2] = 0u; g_pre[3] = 0u;
        g_rank[0] = N1 / 2 - 1; g_rank[1] = N1 / 2;
        g_rank[2] = N2 / 2 - 1; g_rank[3] = N2 / 2;
    }
    for (int i = threadIdx.x; i < 1024; i += blockDim.x)
        ((unsigned*)g_hist4)[i] = 0u;
}

__global__ void k_hist4(const float* __restrict__ w1, const float* __restrict__ w2,
                        int level) {
    __shared__ unsigned sh[4][256];
    for (int i = threadIdx.x; i < 1024; i += blockDim.x) ((unsigned*)sh)[i] = 0u;
    __syncthreads();
    const unsigned maskHigh = (level == 3) ? 0u : (0xFFFFFFFFu << ((level + 1) * 8));
    const int shift = level * 8;
#pragma unroll
    for (int ti = 0; ti < 2; ++ti) {
        const float4* w4 = (const float4*)(ti == 0 ? w1 : w2);
        const unsigned n4 = (ti == 0 ? N1 : N2) / 4;
        const unsigned p0 = g_pre[2 * ti]     & maskHigh;
        const unsigned p1 = g_pre[2 * ti + 1] & maskHigh;
        const bool same = (p0 == p1);
        unsigned* h0 = sh[2 * ti];
        unsigned* h1 = sh[2 * ti + 1];
        for (unsigned i = blockIdx.x * blockDim.x + threadIdx.x; i < n4;
             i += gridDim.x * blockDim.x) {
            float4 v = w4[i];
            unsigned u0 = __float_as_uint(v.x) & 0x7FFFFFFFu;
            unsigned u1 = __float_as_uint(v.y) & 0x7FFFFFFFu;
            unsigned u2 = __float_as_uint(v.z) & 0x7FFFFFFFu;
            unsigned u3 = __float_as_uint(v.w) & 0x7FFFFFFFu;
            if ((u0 & maskHigh) == p0) atomicAdd(&h0[(u0 >> shift) & 255u], 1u);
            if ((u1 & maskHigh) == p0) atomicAdd(&h0[(u1 >> shift) & 255u], 1u);
            if ((u2 & maskHigh) == p0) atomicAdd(&h0[(u2 >> shift) & 255u], 1u);
            if ((u3 & maskHigh) == p0) atomicAdd(&h0[(u3 >> shift) & 255u], 1u);
            if (!same) {
                if ((u0 & maskHigh) == p1) atomicAdd(&h1[(u0 >> shift) & 255u], 1u);
                if ((u1 & maskHigh) == p1) atomicAdd(&h1[(u1 >> shift) & 255u], 1u);
                if ((u2 & maskHigh) == p1) atomicAdd(&h1[(u2 >> shift) & 255u], 1u);
                if ((u3 & maskHigh) == p1) atomicAdd(&h1[(u3 >> shift) & 255u], 1u);
            }
        }
    }
    __syncthreads();
    for (int i = threadIdx.x; i < 256; i += blockDim.x) {
#pragma unroll
        for (int r = 0; r < 4; ++r)
            if (sh[r][i]) atomicAdd(&g_hist4[r][i], sh[r][i]);
    }
}

// parallel pick: 256-thread scan over 4 histograms
__global__ void k_pick4(int level) {
    __shared__ unsigned scans[4][256];
    const int ti = threadIdx.x;
    const unsigned maskHigh = (level == 3) ? 0u : (0xFFFFFFFFu << ((level + 1) * 8));
    const bool same0 = ((g_pre[0] ^ g_pre[1]) & maskHigh) == 0u;
    const bool same1 = ((g_pre[2] ^ g_pre[3]) & maskHigh) == 0u;
    unsigned kk0 = g_rank[0], kk1 = g_rank[1], kk2 = g_rank[2], kk3 = g_rank[3];
    const unsigned c0 = g_hist4[0][ti];
    const unsigned c1 = same0 ? c0 : g_hist4[1][ti];
    const unsigned c2 = g_hist4[2][ti];
    const unsigned c3 = same1 ? c2 : g_hist4[3][ti];
    scans[0][ti] = c0; scans[1][ti] = c1; scans[2][ti] = c2; scans[3][ti] = c3;
    __syncthreads();
    for (int off = 1; off < 256; off <<= 1) {
        unsigned v0 = (ti >= off) ? scans[0][ti - off] : 0u;
        unsigned v1 = (ti >= off) ? scans[1][ti - off] : 0u;
        unsigned v2 = (ti >= off) ? scans[2][ti - off] : 0u;
        unsigned v3 = (ti >= off) ? scans[3][ti - off] : 0u;
        __syncthreads();
        scans[0][ti] += v0; scans[1][ti] += v1;
        scans[2][ti] += v2; scans[3][ti] += v3;
        __syncthreads();
    }
#define PICK1(r, cc, sidx)                                                     \
    { unsigned incl = scans[sidx][ti], excl = incl - (cc);                     \
      unsigned kr = (r == 0) ? kk0 : (r == 1) ? kk1 : (r == 2) ? kk2 : kk3;    \
      if ((cc) && excl <= kr && kr < incl) {                                   \
          atomicOr(&g_pre[r], (unsigned)ti << (level * 8));                    \
          g_rank[r] = kr - excl;                                               \
      } }
    PICK1(0, c0, 0)
    PICK1(1, c1, (same0 ? 0 : 1))
    PICK1(2, c2, 2)
    PICK1(3, c3, (same1 ? 2 : 3))
#undef PICK1
#pragma unroll
    for (int r = 0; r < 4; ++r) g_hist4[r][ti] = 0u;
    __syncthreads();
    if (level == 0 && ti == 0) {
        g_sc[0] = fmaxf(0.5f * (__uint_as_float(g_pre[0]) + __uint_as_float(g_pre[1])), 1e-8f);
        g_sc[1] = fmaxf(0.5f * (__uint_as_float(g_pre[2]) + __uint_as_float(g_pre[3])), 1e-8f);
    }
}

// ---------------- ternary quantization: codes {-1,0,+1} as fp16 (exact) -----
__global__ void k_quant(const float* __restrict__ w, unsigned n, int sidx, int which) {
    __half* q = (which == 0) ? g_w1q : g_w2q;
    const float s = g_sc[sidx];
    for (unsigned i = blockIdx.x * blockDim.x + threadIdx.x; i < n;
         i += gridDim.x * blockDim.x) {
        float t = rintf(w[i] / s);              // round-half-even == jnp.round
        t = fminf(fmaxf(t, -1.0f), 1.0f);
        q[i] = __float2half(t);
    }
}

// ---------------- x fp32 -> fp16 --------------------------------------------
__global__ void k_cvt(const float* __restrict__ x, unsigned n2) {
    __half2* o2 = (__half2*)g_xh;
    for (unsigned i = blockIdx.x * blockDim.x + threadIdx.x; i < n2;
         i += gridDim.x * blockDim.x) {
        float2 v = ((const float2*)x)[i];
        o2[i] = __floats2half2_rn(v.x, v.y);
    }
}

// ---------------- BN epilogue constants (scale s folded into multiplier) ----
__global__ void k_bnparams(const float* __restrict__ g, const float* __restrict__ b,
                           const float* __restrict__ m, const float* __restrict__ v,
                           int n, int sidx, int which) {
    float* A  = (which == 0) ? g_A1 : g_A2;
    float* Bc = (which == 0) ? g_B1 : g_B2;
    const float s = g_sc[sidx];
    int i = blockIdx.x * blockDim.x + threadIdx.x;
    if (i < n) {
        float inv = g[i] * __frsqrt_rn(v[i] + 1e-5f);
        A[i]  = inv * s;
        Bc[i] = b[i] - m[i] * inv;
    }
}

// ---------------- fused tensor-core GEMM + BN + SiLU ------------------------
// mma.sync.m16n8k16 fp16/fp32-acc. Block tile 256x64, 8 warps as 4(M) x 2(N),
// warp tile 64x32. 4-stage cp.async pipeline (R14-verified structure).

__device__ __forceinline__ float silu(float y) {
    return y / (1.0f + expf(-y));
}

extern __shared__ __align__(16) char dynsmem[];

template<int LAYER>
__global__ __launch_bounds__(256)
void k_gemm_mma(float* __restrict__ OutExt) {
    constexpr int K = (LAYER == 1) ? C1_ : KCAT;
    const __half* __restrict__ Wq = (LAYER == 1) ? g_w1q : g_w2q;
    const float* __restrict__ Ae = (LAYER == 1) ? g_A1  : g_A2;
    const float* __restrict__ Be = (LAYER == 1) ? g_B1  : g_B2;

    const int b   = blockIdx.z;
    const int n0  = blockIdx.x * BN;
    const int m0  = blockIdx.y * BM;
    const int tid = threadIdx.x;
    const int lane = tid & 31;
    const int wid  = tid >> 5;
    const int wm = wid >> 1;   // 0..3 : 64-row slice
    const int wn = wid & 1;    // 0..1 : 32-col slice

    typedef __half AsT[BM][BK + 8];
    typedef __half BsT[BK][BN + 8];
    AsT* As = reinterpret_cast<AsT*>(dynsmem);                                // [NSTAGE]
    BsT* Bs = reinterpret_cast<BsT*>(dynsmem + NSTAGE * sizeof(AsT));         // [NSTAGE]

    // 64 named accumulators
    DECL_C(c00); DECL_C(c01); DECL_C(c02); DECL_C(c03);
    DECL_C(c10); DECL_C(c11); DECL_C(c12); DECL_C(c13);
    DECL_C(c20); DECL_C(c21); DECL_C(c22); DECL_C(c23);
    DECL_C(c30); DECL_C(c31); DECL_C(c32); DECL_C(c33);
    // fragment regs (named scalars)
    DECL_BF(0); DECL_BF(1);
    DECL_AF(0,0); DECL_AF(0,1); DECL_AF(0,2); DECL_AF(0,3);
    DECL_AF(1,0); DECL_AF(1,1); DECL_AF(1,2); DECL_AF(1,3);

    // async copy mappings (all 16B chunks)
    const int ar  = tid >> 2;        // 0..63  (A rows, +64/+128/+192 passes)
    const int ac  = tid & 3;
    const int br  = tid >> 3;        // 0..31  (B rows)
    const int bc  = tid & 7;

    auto issue = [&](int t, int s) {
        const int k0 = t * BK;
        cp16(&As[s][ar      ][ac * 8], Wq + (size_t)(m0 + ar      ) * K + k0 + ac * 8);
        cp16(&As[s][ar +  64][ac * 8], Wq + (size_t)(m0 + ar +  64) * K + k0 + ac * 8);
        cp16(&As[s][ar + 128][ac * 8], Wq + (size_t)(m0 + ar + 128) * K + k0 + ac * 8);
        cp16(&As[s][ar + 192][ac * 8], Wq + (size_t)(m0 + ar + 192) * K + k0 + ac * 8);
        const __half* src; size_t off;
        if (LAYER == 1) {
            src = g_xh;
            off = ((size_t)b * K + (k0 + br)) * HWp;
        } else {
            int kk = k0 + br;
            int si = kk >> 9, cc = kk & 511;
            src = (si == 0) ? g_h : (si == 1) ? g_y1 : (si == 2) ? g_y2 : g_y3;
            off = ((size_t)b * HID_ + cc) * HWp;
        }
        cp16(&Bs[s][br][bc * 8], src + off + n0 + bc * 8);
        cp_commit();
    };

    constexpr int NT = K / BK;
    issue(0, 0); issue(1, 1); issue(2, 2);

    const int lr = lane & 15;
    const int lc = (lane >> 4) * 8;

    for (int t = 0; t < NT; ++t) {
        const int s = t & (NSTAGE - 1);
        // tail-aware wait: guarantee chunk t's loads have landed
        if (t < NT - 2)       cp_wait<2>();
        else if (t == NT - 2) cp_wait<1>();
        else                  cp_wait<0>();
        __syncthreads();
        if (t + NSTAGE - 1 < NT) issue(t + NSTAGE - 1, (t + NSTAGE - 1) & (NSTAGE - 1));

        LOADG(0, 0)
        LOADG(1, 16)
        MMAG(0);
        MMAG(1);
    }

    // epilogue: BN + SiLU (named scalars only)
#define STORE_TILE(cc, mtv, ntv) do {                                          \
        const int mrow = m0 + wm * 64 + (mtv) * 16 + (lane >> 2);              \
        const int col  = n0 + wn * 32 + (ntv) * 8 + (lane & 3) * 2;            \
        const float A0 = Ae[mrow],     Bv0 = Be[mrow];                         \
        const float A1 = Ae[mrow + 8], Bv1 = Be[mrow + 8];                     \
        float v0 = silu(cc##0 * A0 + Bv0), v1 = silu(cc##1 * A0 + Bv0);        \
        float v2 = silu(cc##2 * A1 + Bv1), v3 = silu(cc##3 * A1 + Bv1);        \
        if (LAYER == 1) {                                                      \
            *(__half2*)(g_h + ((size_t)b * HID_ + mrow) * HWp + col) =         \
                __floats2half2_rn(v0, v1);                                     \
            *(__half2*)(g_h + ((size_t)b * HID_ + mrow + 8) * HWp + col) =     \
                __floats2half2_rn(v2, v3);                                     \
        } else {                                                               \
            *(float2*)(OutExt + ((size_t)b * C2_ + mrow) * HWp + col) =        \
                make_float2(v0, v1);                                           \
            *(float2*)(OutExt + ((size_t)b * C2_ + mrow + 8) * HWp + col) =    \
                make_float2(v2, v3);                                           \
        }                                                                      \
    } while (0)

    STORE_TILE(c00, 0, 0); STORE_TILE(c01, 0, 1); STORE_TILE(c02, 0, 2); STORE_TILE(c03, 0, 3);
    STORE_TILE(c10, 1, 0); STORE_TILE(c11, 1, 1); STORE_TILE(c12, 1, 2); STORE_TILE(c13, 1, 3);
    STORE_TILE(c20, 2, 0); STORE_TILE(c21, 2, 1); STORE_TILE(c22, 2, 2); STORE_TILE(c23, 2, 3);
    STORE_TILE(c30, 3, 0); STORE_TILE(c31, 3, 1); STORE_TILE(c32, 3, 2); STORE_TILE(c33, 3, 3);
#undef STORE_TILE
}

// ---------------- fused 3x cascaded 5x5 maxpool (one plane per block) --------
// Loads the h plane once, runs all three pool stages in shared memory,
// stores y1, y2, y3. Saves two full plane-set reads vs separate kernels.
__global__ __launch_bounds__(256)
void k_pool3() {
    __shared__ __half p[HWp];
    __shared__ __half tmp[HWp];
    const size_t plane = (size_t)blockIdx.x * HWp;
    const int tid = threadIdx.x;

    for (int i = tid; i < HWp; i += 256) p[i] = g_h[plane + i];
    __syncthreads();

#pragma unroll
    for (int stage = 0; stage < 3; ++stage) {
        // x-pass: p -> tmp
        for (int i = tid; i < HWp; i += 256) {
            int y = i / 40, x = i % 40;
            __half m = p[i];
            int x0 = max(x - 2, 0), x1 = min(x + 2, 39);
            for (int xx = x0; xx <= x1; ++xx) m = __hmax(m, p[y * 40 + xx]);
            tmp[i] = m;
        }
        __syncthreads();
        // y-pass: tmp -> p (p now holds the pooled plane)
        for (int i = tid; i < HWp; i += 256) {
            int y = i / 40, x = i % 40;
            __half m = tmp[i];
            int y0 = max(y - 2, 0), y1 = min(y + 2, 39);
            for (int yy = y0; yy <= y1; ++yy) m = __hmax(m, tmp[yy * 40 + x]);
            p[i] = m;
        }
        __syncthreads();
        __half* out = (stage == 0) ? g_y1 : (stage == 1) ? g_y2 : g_y3;
        for (int i = tid; i < HWp; i += 256) out[plane + i] = p[i];
        // no sync needed before next x-pass reads p: next loop only reads p,
        // and all threads passed the post-y-pass barrier; stores above read p too.
        __syncthreads();
    }
}

// ---------------- host orchestration (all graph-capturable launches) --------
extern "C" void kernel_launch(void* const* d_in, const int* in_sizes, int n_in,
                              void* d_out, int out_size) {
    const float* x  = (const float*)d_in[0];
    const float* w1 = (const float*)d_in[1];
    const float* g1 = (const float*)d_in[2];
    const float* b1 = (const float*)d_in[3];
    const float* m1 = (const float*)d_in[4];
    const float* v1 = (const float*)d_in[5];
    const float* w2 = (const float*)d_in[6];
    const float* g2 = (const float*)d_in[7];
    const float* b2 = (const float*)d_in[8];
    const float* m2 = (const float*)d_in[9];
    const float* v2 = (const float*)d_in[10];
    float* out = (float*)d_out;

    // allow >48K dynamic smem (host attr; idempotent, graph-capture-safe)
    cudaFuncSetAttribute(k_gemm_mma<1>, cudaFuncAttributeMaxDynamicSharedMemorySize, SMEM_GEMM);
    cudaFuncSetAttribute(k_gemm_mma<2>, cudaFuncAttributeMaxDynamicSharedMemorySize, SMEM_GEMM);

    // convert activations to fp16
    k_cvt<<<2048, 256>>>(x, (unsigned)((size_t)B_ * C1_ * HWp / 2));

    // exact medians: BOTH tensors in one 4-way radix-select sequence
    k_selinit4<<<1, 256>>>();
    for (int level = 3; level >= 0; --level) {
        k_hist4<<<512, 256>>>(w1, w2, level);
        k_pick4<<<1, 256>>>(level);
    }

    // quantize weights to ternary fp16 codes
    k_quant<<<1024, 256>>>(w1, N1, 0, 0);
    k_quant<<<2048, 256>>>(w2, N2, 1, 1);

    // BN epilogue constants (fold s into multiplier)
    k_bnparams<<<(HID_ + 255) / 256, 256>>>(g1, b1, m1, v1, HID_, 0, 0);
    k_bnparams<<<(C2_  + 255) / 256, 256>>>(g2, b2, m2, v2, C2_,  1, 1);

    // layer 1: conv1x1 + BN + SiLU -> g_h (fp16)
    {
        dim3 grid(HWp / BN, HID_ / BM, B_);
        k_gemm_mma<1><<<grid, 256, SMEM_GEMM>>>(nullptr);
    }

    // all three cascaded 5x5 maxpools in ONE kernel (plane stays in smem)
    k_pool3<<<B_ * HID_, 256>>>();

    // layer 2: conv1x1 over virtual concat + BN + SiLU -> out (fp32)
    {
        dim3 grid(HWp / BN, C2_ / BM, B_);
        k_gemm_mma<2><<<grid, 256, SMEM_GEMM>>>(out);
    }
}